// round 5
// baseline (speedup 1.0000x reference)
#include <cuda_runtime.h>
#include <cuda_bf16.h>
#include <cstdint>

// ---------------------------------------------------------------------------
// Mamba block forward.  B=2, L=2048, d_model=512, d_inner=1024, d_state=16,
// dt_rank=32, d_conv=4.
// Launches: 1 gemm_mma1   in_proj (tf32 mma, cvt-in-kernel)
//           2 conv_xproj  conv+silu + x_proj fused (+ out_proj_w tf32 cvt)
//           3 gemm_nt4    dt_proj + softplus
//           4 scan_kernel selective scan (writes tf32-rounded g_y)
//           5 gemm_mma6   out_proj (tf32 mma, cp.async 2-stage pipeline)
// ---------------------------------------------------------------------------

#define BATCH    2
#define SEQLEN   2048
#define DMODEL   512
#define DINNER   1024
#define DSTATE   16
#define DTRANK   32
#define DCONV    4
#define MROWS    (BATCH * SEQLEN)        // 4096

// Scratch (device-global; no runtime allocation allowed)
__device__ float g_xz[(size_t)MROWS * 2 * DINNER];    // [4096, 2048]  xs | z
__device__ float g_xs[(size_t)MROWS * DINNER];        // conv+silu output
__device__ float g_xdbl[(size_t)MROWS * 64];          // [4096, 64]
__device__ float g_delta[(size_t)MROWS * DINNER];     // softplus(dt@W + b)
__device__ float g_y[(size_t)MROWS * DINNER];         // scan output (tf32-rounded)
__device__ uint32_t g_w6tf[(size_t)DMODEL * DINNER];  // out_proj_w in tf32

// ---------------------------------------------------------------------------
__device__ __forceinline__ uint32_t f2tf32(float f) {
    uint32_t r;
    asm("cvt.rna.tf32.f32 %0, %1;" : "=r"(r) : "f"(f));
    return r;
}

__device__ __forceinline__ void mma_tf32(float c[4], const uint32_t a[4],
                                         uint32_t b0, uint32_t b1) {
    asm volatile(
        "mma.sync.aligned.m16n8k8.row.col.f32.tf32.tf32.f32 "
        "{%0,%1,%2,%3}, {%4,%5,%6,%7}, {%8,%9}, {%0,%1,%2,%3};"
        : "+f"(c[0]), "+f"(c[1]), "+f"(c[2]), "+f"(c[3])
        : "r"(a[0]), "r"(a[1]), "r"(a[2]), "r"(a[3]), "r"(b0), "r"(b1));
}

__device__ __forceinline__ void cp16(uint32_t dst_smem, const void* src) {
    asm volatile("cp.async.cg.shared.global [%0], [%1], 16;\n"
                 :: "r"(dst_smem), "l"(src));
}

// ---------------------------------------------------------------------------
// Stage 1: in_proj, tf32 mma, register-staged cvt (R4 design).
// C[m,n] = sum_k x[m,k] * W[n,k];  M=4096, N=2048, K=512.
// ---------------------------------------------------------------------------
__global__ void __launch_bounds__(256)
gemm_mma1(const float* __restrict__ A, const float* __restrict__ W)
{
    constexpr int BM = 128, BN = 128, BK = 16, SST = BK + 4;
    constexpr int lda = DMODEL, ldw = DMODEL, ldc = 2 * DINNER, K = DMODEL;
    float* C = g_xz;

    __shared__ __align__(16) uint32_t As[BM][SST];
    __shared__ __align__(16) uint32_t Bs[BN][SST];

    const int tid = threadIdx.x;
    const int lane = tid & 31;
    const int wid = tid >> 5;
    const int wm = (wid & 3) * 32;
    const int wn = (wid >> 2) * 64;
    const int g  = lane >> 2;
    const int tg = lane & 3;

    const int m0 = blockIdx.y * BM;
    const int n0 = blockIdx.x * BN;

    const int lr0 = tid >> 2;
    const int lr1 = lr0 + 64;
    const int lc4 = (tid & 3) * 4;

    const float* Ar0 = A + (size_t)(m0 + lr0) * lda + lc4;
    const float* Ar1 = A + (size_t)(m0 + lr1) * lda + lc4;
    const float* Wr0 = W + (size_t)(n0 + lr0) * ldw + lc4;
    const float* Wr1 = W + (size_t)(n0 + lr1) * ldw + lc4;

    float c[2][8][4];
#pragma unroll
    for (int i = 0; i < 2; i++)
#pragma unroll
        for (int j = 0; j < 8; j++)
#pragma unroll
            for (int r = 0; r < 4; r++) c[i][j][r] = 0.f;

    float4 av0 = *(const float4*)(Ar0);
    float4 av1 = *(const float4*)(Ar1);
    float4 wv0 = *(const float4*)(Wr0);
    float4 wv1 = *(const float4*)(Wr1);

#pragma unroll 1
    for (int k0 = 0; k0 < K; k0 += BK) {
        __syncthreads();
        {
            uint4 p;
            p.x = f2tf32(av0.x); p.y = f2tf32(av0.y);
            p.z = f2tf32(av0.z); p.w = f2tf32(av0.w);
            *(uint4*)&As[lr0][lc4] = p;
            p.x = f2tf32(av1.x); p.y = f2tf32(av1.y);
            p.z = f2tf32(av1.z); p.w = f2tf32(av1.w);
            *(uint4*)&As[lr1][lc4] = p;
            p.x = f2tf32(wv0.x); p.y = f2tf32(wv0.y);
            p.z = f2tf32(wv0.z); p.w = f2tf32(wv0.w);
            *(uint4*)&Bs[lr0][lc4] = p;
            p.x = f2tf32(wv1.x); p.y = f2tf32(wv1.y);
            p.z = f2tf32(wv1.z); p.w = f2tf32(wv1.w);
            *(uint4*)&Bs[lr1][lc4] = p;
        }
        __syncthreads();

        if (k0 + BK < K) {
            av0 = *(const float4*)(Ar0 + k0 + BK);
            av1 = *(const float4*)(Ar1 + k0 + BK);
            wv0 = *(const float4*)(Wr0 + k0 + BK);
            wv1 = *(const float4*)(Wr1 + k0 + BK);
        }

#pragma unroll
        for (int kk = 0; kk < 2; kk++) {
            const int kb = kk * 8;
            uint32_t a[2][4];
#pragma unroll
            for (int i = 0; i < 2; i++) {
                const int m = wm + i * 16 + g;
                a[i][0] = As[m][kb + tg];
                a[i][1] = As[m + 8][kb + tg];
                a[i][2] = As[m][kb + tg + 4];
                a[i][3] = As[m + 8][kb + tg + 4];
            }
#pragma unroll
            for (int j = 0; j < 8; j++) {
                const int n = wn + j * 8 + g;
                const uint32_t b0 = Bs[n][kb + tg];
                const uint32_t b1 = Bs[n][kb + tg + 4];
                mma_tf32(c[0][j], a[0], b0, b1);
                mma_tf32(c[1][j], a[1], b0, b1);
            }
        }
    }

#pragma unroll
    for (int i = 0; i < 2; i++) {
        const int mrow0 = m0 + wm + i * 16 + g;
#pragma unroll
        for (int j = 0; j < 8; j++) {
            const int ncol = n0 + wn + j * 8 + 2 * tg;
            *(float2*)&C[(size_t)mrow0 * ldc + ncol] =
                make_float2(c[i][j][0], c[i][j][1]);
            *(float2*)&C[(size_t)(mrow0 + 8) * ldc + ncol] =
                make_float2(c[i][j][2], c[i][j][3]);
        }
    }
}

// ---------------------------------------------------------------------------
// Stage 2+3 fused: causal depthwise conv1d + SiLU, then x_proj GEMM
// (row-local: xdbl[m,e] = sum_d xs[m,d] * W1[e,d]).
// Block = 32 rows; loop 16 d-tiles of 64.  Side job: convert a slice of
// out_proj_w to tf32 into g_w6tf for the stage-6 cp.async pipeline.
// ---------------------------------------------------------------------------
__global__ void __launch_bounds__(256)
conv_xproj(const float* __restrict__ conv_w,
           const float* __restrict__ conv_b,
           const float* __restrict__ x_proj_w,
           const float* __restrict__ out_proj_w)
{
    __shared__ float sxs[32][68];
    __shared__ float sw[64][68];

    const int tid = threadIdx.x;
    const int bl0 = blockIdx.x * 32;
    const int tx = tid & 15;          // e / 4
    const int ty = tid >> 4;          // row / 2

    float acc[2][4];
#pragma unroll
    for (int i = 0; i < 2; i++)
#pragma unroll
        for (int j = 0; j < 4; j++) acc[i][j] = 0.f;

#pragma unroll 1
    for (int d0 = 0; d0 < DINNER; d0 += 64) {
        __syncthreads();
        // load W1 tile [64 e][64 d]
#pragma unroll
        for (int it = 0; it < 4; it++) {
            const int idx = tid + it * 256;
            const int e = idx >> 4, c4 = (idx & 15) * 4;
            *(float4*)&sw[e][c4] =
                *(const float4*)&x_proj_w[(size_t)e * DINNER + d0 + c4];
        }
        // conv+silu for 32 rows x 64 d
#pragma unroll
        for (int it = 0; it < 8; it++) {
            const int idx = tid + it * 256;
            const int r = idx >> 6, dc = idx & 63;
            const int bl = bl0 + r;
            const int l = bl & (SEQLEN - 1);
            const int d = d0 + dc;
            float a = conv_b[d];
#pragma unroll
            for (int j = 0; j < DCONV; j++) {
                const int ls = l - (DCONV - 1) + j;
                if (ls >= 0)
                    a = fmaf(g_xz[(size_t)(bl - (DCONV - 1) + j) * (2 * DINNER) + d],
                             conv_w[d * DCONV + j], a);
            }
            const float s = a / (1.f + __expf(-a));
            sxs[r][dc] = s;
            g_xs[(size_t)bl * DINNER + d] = s;
        }
        __syncthreads();
        // accumulate xdbl[r][e] over this d-tile
#pragma unroll
        for (int kk = 0; kk < 64; kk++) {
            float ar[2], br[4];
#pragma unroll
            for (int i = 0; i < 2; i++) ar[i] = sxs[ty * 2 + i][kk];
#pragma unroll
            for (int j = 0; j < 4; j++) br[j] = sw[tx * 4 + j][kk];
#pragma unroll
            for (int i = 0; i < 2; i++)
#pragma unroll
                for (int j = 0; j < 4; j++)
                    acc[i][j] = fmaf(ar[i], br[j], acc[i][j]);
        }
    }

#pragma unroll
    for (int i = 0; i < 2; i++)
#pragma unroll
        for (int j = 0; j < 4; j++)
            g_xdbl[(size_t)(bl0 + ty * 2 + i) * 64 + tx * 4 + j] = acc[i][j];

    // side job: tf32-convert this block's slice of out_proj_w (4096 floats)
    const size_t base = (size_t)blockIdx.x * 4096;
#pragma unroll
    for (int it = 0; it < 4; it++) {
        const size_t off = base + (size_t)it * 1024 + tid * 4;
        float4 w4 = *(const float4*)&out_proj_w[off];
        uint4 p;
        p.x = f2tf32(w4.x); p.y = f2tf32(w4.y);
        p.z = f2tf32(w4.z); p.w = f2tf32(w4.w);
        *(uint4*)&g_w6tf[off] = p;
    }
}

// ---------------------------------------------------------------------------
// Stage 4: dt_proj + softplus (fp32 SIMT; small K=32).
// ---------------------------------------------------------------------------
__global__ void __launch_bounds__(256)
gemm_nt4(const float* __restrict__ W, const float* __restrict__ bias)
{
    constexpr int BM = 64, BN = 64, BK = 16;
    constexpr int lda = 64, ldw = DTRANK, ldc = DINNER, K = DTRANK;
    const float* A = g_xdbl;
    float* C = g_delta;

    __shared__ float As[BK][BM];
    __shared__ float Bs[BK][BN];

    const int tid = threadIdx.x;
    const int m0 = blockIdx.y * BM;
    const int n0 = blockIdx.x * BN;
    const int tx = tid & 15;
    const int ty = tid >> 4;
    const int lrow = tid >> 2;
    const int lc4 = (tid & 3) * 4;

    float acc[4][4];
#pragma unroll
    for (int i = 0; i < 4; i++)
#pragma unroll
        for (int j = 0; j < 4; j++) acc[i][j] = 0.f;

    const float* Arow = A + (size_t)(m0 + lrow) * lda + lc4;
    const float* Wrow = W + (size_t)(n0 + lrow) * ldw + lc4;

#pragma unroll 1
    for (int k0 = 0; k0 < K; k0 += BK) {
        float4 av = *(const float4*)(Arow + k0);
        float4 wv = *(const float4*)(Wrow + k0);
        __syncthreads();
        As[lc4 + 0][lrow] = av.x; As[lc4 + 1][lrow] = av.y;
        As[lc4 + 2][lrow] = av.z; As[lc4 + 3][lrow] = av.w;
        Bs[lc4 + 0][lrow] = wv.x; Bs[lc4 + 1][lrow] = wv.y;
        Bs[lc4 + 2][lrow] = wv.z; Bs[lc4 + 3][lrow] = wv.w;
        __syncthreads();
#pragma unroll
        for (int kk = 0; kk < BK; kk++) {
            float4 a4 = *(const float4*)&As[kk][ty * 4];
            float4 b4 = *(const float4*)&Bs[kk][tx * 4];
            float ar[4] = {a4.x, a4.y, a4.z, a4.w};
            float br[4] = {b4.x, b4.y, b4.z, b4.w};
#pragma unroll
            for (int i = 0; i < 4; i++)
#pragma unroll
                for (int j = 0; j < 4; j++)
                    acc[i][j] = fmaf(ar[i], br[j], acc[i][j]);
        }
    }

#pragma unroll
    for (int i = 0; i < 4; i++) {
        const int m = m0 + ty * 4 + i;
#pragma unroll
        for (int j = 0; j < 4; j++) {
            const int n = n0 + tx * 4 + j;
            float v = acc[i][j] + bias[n];
            v = (v > 20.f) ? v : log1pf(__expf(v));   // softplus
            C[(size_t)m * ldc + n] = v;
        }
    }
}

// ---------------------------------------------------------------------------
// Stage 5: selective scan, chunked double-buffered prefetch (R4 design).
// Output stored tf32-rounded so stage 6 can consume it without cvt.
// ---------------------------------------------------------------------------
#define SCH 8
__global__ void __launch_bounds__(128)
scan_kernel(const float* __restrict__ A_log,
            const float* __restrict__ D_param)
{
    const int tid = threadIdx.x;
    const int half = tid >> 4;
    const int n = tid & 15;
    const int hw = blockIdx.x * 8 + half;
    const int b = hw >> 10;
    const int d = hw & (DINNER - 1);

    const float A_dn = -__expf(A_log[d * DSTATE + n]);
    const float Dd = D_param[d];

    const float* xd = g_xdbl + (size_t)b * SEQLEN * 64;
    const float* dl = g_delta + (size_t)b * SEQLEN * DINNER + d;
    const float* us = g_xs + (size_t)b * SEQLEN * DINNER + d;
    const float* zp = g_xz + (size_t)b * SEQLEN * (2 * DINNER) + DINNER + d;
    float* yp = g_y + (size_t)b * SEQLEN * DINNER + d;

    float bdt[2][SCH], bu[2][SCH], bB[2][SCH], bC[2][SCH], bz[2][SCH];

#pragma unroll
    for (int j = 0; j < SCH; j++) {
        bdt[0][j] = dl[(size_t)j * DINNER];
        bu[0][j]  = us[(size_t)j * DINNER];
        bB[0][j]  = xd[j * 64 + DTRANK + n];
        bC[0][j]  = xd[j * 64 + DTRANK + DSTATE + n];
        bz[0][j]  = zp[(size_t)j * (2 * DINNER)];
    }

    float h = 0.f;
    int pb = 0;
#pragma unroll 1
    for (int l0 = 0; l0 < SEQLEN; l0 += SCH) {
        const int nb = pb ^ 1;
        if (l0 + SCH < SEQLEN) {
            const int base = l0 + SCH;
#pragma unroll
            for (int j = 0; j < SCH; j++) {
                bdt[nb][j] = dl[(size_t)(base + j) * DINNER];
                bu[nb][j]  = us[(size_t)(base + j) * DINNER];
                bB[nb][j]  = xd[(base + j) * 64 + DTRANK + n];
                bC[nb][j]  = xd[(base + j) * 64 + DTRANK + DSTATE + n];
                bz[nb][j]  = zp[(size_t)(base + j) * (2 * DINNER)];
            }
        }
#pragma unroll
        for (int j = 0; j < SCH; j++) {
            const float dt_c = bdt[pb][j];
            const float dA = __expf(dt_c * A_dn);
            h = fmaf(dA, h, dt_c * bu[pb][j] * bB[pb][j]);
            float p = h * bC[pb][j];
            p += __shfl_xor_sync(0xffffffffu, p, 8, 16);
            p += __shfl_xor_sync(0xffffffffu, p, 4, 16);
            p += __shfl_xor_sync(0xffffffffu, p, 2, 16);
            p += __shfl_xor_sync(0xffffffffu, p, 1, 16);
            if (n == 0) {
                const float z = bz[pb][j];
                const float sz = z / (1.f + __expf(-z));
                const float v = (p + bu[pb][j] * Dd) * sz;
                yp[(size_t)(l0 + j) * DINNER] = __uint_as_float(f2tf32(v));
            }
        }
        pb = nb;
    }
}

// ---------------------------------------------------------------------------
// Stage 6: out_proj, tf32 mma with 2-stage cp.async pipeline, no in-loop cvt.
// A = g_y (tf32-rounded), W = g_w6tf (tf32).  M=4096, N=512, K=1024.
// ---------------------------------------------------------------------------
__global__ void __launch_bounds__(256)
gemm_mma6(float* __restrict__ C)
{
    constexpr int BM = 128, BN = 128, BK = 16, SST = BK + 4;
    constexpr int lda = DINNER, ldw = DINNER, ldc = DMODEL;
    constexpr int NT = DINNER / BK;   // 64 ktiles

    __shared__ __align__(16) uint32_t As[2][BM][SST];
    __shared__ __align__(16) uint32_t Bs[2][BN][SST];

    const int tid = threadIdx.x;
    const int lane = tid & 31;
    const int wid = tid >> 5;
    const int wm = (wid & 3) * 32;
    const int wn = (wid >> 2) * 64;
    const int g  = lane >> 2;
    const int tg = lane & 3;

    const int m0 = blockIdx.y * BM;
    const int n0 = blockIdx.x * BN;

    const int lr0 = tid >> 2;
    const int lr1 = lr0 + 64;
    const int lc4 = (tid & 3) * 4;

    const float* Ar0 = g_y + (size_t)(m0 + lr0) * lda + lc4;
    const float* Ar1 = g_y + (size_t)(m0 + lr1) * lda + lc4;
    const uint32_t* Wr0 = g_w6tf + (size_t)(n0 + lr0) * ldw + lc4;
    const uint32_t* Wr1 = g_w6tf + (size_t)(n0 + lr1) * ldw + lc4;

    uint32_t sA0 = (uint32_t)__cvta_generic_to_shared(&As[0][lr0][lc4]);
    uint32_t sA1 = (uint32_t)__cvta_generic_to_shared(&As[0][lr1][lc4]);
    uint32_t sB0 = (uint32_t)__cvta_generic_to_shared(&Bs[0][lr0][lc4]);
    uint32_t sB1 = (uint32_t)__cvta_generic_to_shared(&Bs[0][lr1][lc4]);
    constexpr uint32_t STAGE_A = sizeof(uint32_t) * BM * SST;  // bytes per stage
    constexpr uint32_t STAGE_B = sizeof(uint32_t) * BN * SST;

    float c[2][8][4];
#pragma unroll
    for (int i = 0; i < 2; i++)
#pragma unroll
        for (int j = 0; j < 8; j++)
#pragma unroll
            for (int r = 0; r < 4; r++) c[i][j][r] = 0.f;

    // prologue: stage 0
    cp16(sA0, Ar0); cp16(sA1, Ar1);
    cp16(sB0, Wr0); cp16(sB1, Wr1);
    asm volatile("cp.async.commit_group;\n" ::);

#pragma unroll 1
    for (int kt = 0; kt < NT; kt++) {
        const int s = kt & 1;
        if (kt + 1 < NT) {
            const int k = (kt + 1) * BK;
            const uint32_t so = (uint32_t)((kt + 1) & 1);
            cp16(sA0 + so * STAGE_A, Ar0 + k);
            cp16(sA1 + so * STAGE_A, Ar1 + k);
            cp16(sB0 + so * STAGE_B, Wr0 + k);
            cp16(sB1 + so * STAGE_B, Wr1 + k);
            asm volatile("cp.async.commit_group;\n" ::);
            asm volatile("cp.async.wait_group 1;\n" ::);
        } else {
            asm volatile("cp.async.wait_group 0;\n" ::);
        }
        __syncthreads();

#pragma unroll
        for (int kk = 0; kk < 2; kk++) {
            const int kb = kk * 8;
            uint32_t a[2][4];
#pragma unroll
            for (int i = 0; i < 2; i++) {
                const int m = wm + i * 16 + g;
                a[i][0] = As[s][m][kb + tg];
                a[i][1] = As[s][m + 8][kb + tg];
                a[i][2] = As[s][m][kb + tg + 4];
                a[i][3] = As[s][m + 8][kb + tg + 4];
            }
#pragma unroll
            for (int j = 0; j < 8; j++) {
                const int n = wn + j * 8 + g;
                const uint32_t b0 = Bs[s][n][kb + tg];
                const uint32_t b1 = Bs[s][n][kb + tg + 4];
                mma_tf32(c[0][j], a[0], b0, b1);
                mma_tf32(c[1][j], a[1], b0, b1);
            }
        }
        __syncthreads();
    }

#pragma unroll
    for (int i = 0; i < 2; i++) {
        const int mrow0 = m0 + wm + i * 16 + g;
#pragma unroll
        for (int j = 0; j < 8; j++) {
            const int ncol = n0 + wn + j * 8 + 2 * tg;
            *(float2*)&C[(size_t)mrow0 * ldc + ncol] =
                make_float2(c[i][j][0], c[i][j][1]);
            *(float2*)&C[(size_t)(mrow0 + 8) * ldc + ncol] =
                make_float2(c[i][j][2], c[i][j][3]);
        }
    }
}

// ---------------------------------------------------------------------------
extern "C" void kernel_launch(void* const* d_in, const int* in_sizes, int n_in,
                              void* d_out, int out_size)
{
    const float* x          = (const float*)d_in[0];
    const float* in_proj_w  = (const float*)d_in[1];
    const float* conv_w     = (const float*)d_in[2];
    const float* conv_b     = (const float*)d_in[3];
    const float* x_proj_w   = (const float*)d_in[4];
    const float* dt_proj_w  = (const float*)d_in[5];
    const float* dt_proj_b  = (const float*)d_in[6];
    const float* A_log      = (const float*)d_in[7];
    const float* D_param    = (const float*)d_in[8];
    const float* out_proj_w = (const float*)d_in[9];
    float* out = (float*)d_out;

    // 1) in_proj (tf32 mma) -> g_xz [4096,2048]
    gemm_mma1<<<dim3(2 * DINNER / 128, MROWS / 128), 256>>>(x, in_proj_w);

    // 2+3) conv+silu fused with x_proj -> g_xs, g_xdbl  (+ w6 tf32 cvt)
    conv_xproj<<<MROWS / 32, 256>>>(conv_w, conv_b, x_proj_w, out_proj_w);

    // 4) dt_proj + softplus -> g_delta [4096,1024]
    gemm_nt4<<<dim3(DINNER / 64, MROWS / 64), 256>>>(dt_proj_w, dt_proj_b);

    // 5) selective scan + skip + gate -> g_y (tf32-rounded)
    scan_kernel<<<BATCH * DINNER / 8, 128>>>(A_log, D_param);

    // 6) out_proj (tf32 mma, cp.async pipeline) -> out [4096,512]
    gemm_mma6<<<dim3(DMODEL / 128, MROWS / 128), 256>>>(out);
}

// round 6
// speedup vs baseline: 1.8231x; 1.8231x over previous
#include <cuda_runtime.h>
#include <cuda_bf16.h>
#include <cstdint>

// ---------------------------------------------------------------------------
// Mamba block forward.  B=2, L=2048, d_model=512, d_inner=1024, d_state=16,
// dt_rank=32, d_conv=4.
// Launches: 1 gemm_mma1   in_proj (tf32 mma)
//           2 conv_xproj  conv+silu + x_proj fused; writes xs_t, z_t (transposed)
//           3 gemm_nt4    dt_proj + softplus -> delta_t (transposed)
//           4 scan_kernel selective scan, cp.async pipelined streams
//           5 gemm_mma6   out_proj (tf32 mma, cp.async)
// ---------------------------------------------------------------------------

#define BATCH    2
#define SEQLEN   2048
#define DMODEL   512
#define DINNER   1024
#define DSTATE   16
#define DTRANK   32
#define DCONV    4
#define MROWS    (BATCH * SEQLEN)        // 4096
#define NCHAN    (BATCH * DINNER)        // 2048 scan channels

// Scratch (device-global; no runtime allocation allowed)
__device__ float g_xz[(size_t)MROWS * 2 * DINNER];    // [4096, 2048]  xs | z
__device__ float g_xst[(size_t)NCHAN * SEQLEN];       // xs transposed [ch][l]
__device__ float g_zt[(size_t)NCHAN * SEQLEN];        // z transposed [ch][l]
__device__ float g_xdbl[(size_t)MROWS * 64];          // [4096, 64]
__device__ float g_deltat[(size_t)NCHAN * SEQLEN];    // delta transposed [ch][l]
__device__ float g_y[(size_t)MROWS * DINNER];         // scan output (tf32-rounded)
__device__ uint32_t g_w6tf[(size_t)DMODEL * DINNER];  // out_proj_w in tf32

// ---------------------------------------------------------------------------
__device__ __forceinline__ uint32_t f2tf32(float f) {
    uint32_t r;
    asm("cvt.rna.tf32.f32 %0, %1;" : "=r"(r) : "f"(f));
    return r;
}

__device__ __forceinline__ void mma_tf32(float c[4], const uint32_t a[4],
                                         uint32_t b0, uint32_t b1) {
    asm volatile(
        "mma.sync.aligned.m16n8k8.row.col.f32.tf32.tf32.f32 "
        "{%0,%1,%2,%3}, {%4,%5,%6,%7}, {%8,%9}, {%0,%1,%2,%3};"
        : "+f"(c[0]), "+f"(c[1]), "+f"(c[2]), "+f"(c[3])
        : "r"(a[0]), "r"(a[1]), "r"(a[2]), "r"(a[3]), "r"(b0), "r"(b1));
}

__device__ __forceinline__ void cp16(uint32_t dst_smem, const void* src) {
    asm volatile("cp.async.cg.shared.global [%0], [%1], 16;\n"
                 :: "r"(dst_smem), "l"(src));
}

// ---------------------------------------------------------------------------
// Stage 1: in_proj, tf32 mma.  C[m,n] = sum_k x[m,k] W[n,k]; 4096x2048x512.
// ---------------------------------------------------------------------------
__global__ void __launch_bounds__(256)
gemm_mma1(const float* __restrict__ A, const float* __restrict__ W)
{
    constexpr int BM = 128, BN = 128, BK = 16, SST = BK + 4;
    constexpr int lda = DMODEL, ldw = DMODEL, ldc = 2 * DINNER, K = DMODEL;
    float* C = g_xz;

    __shared__ __align__(16) uint32_t As[BM][SST];
    __shared__ __align__(16) uint32_t Bs[BN][SST];

    const int tid = threadIdx.x;
    const int lane = tid & 31;
    const int wid = tid >> 5;
    const int wm = (wid & 3) * 32;
    const int wn = (wid >> 2) * 64;
    const int g  = lane >> 2;
    const int tg = lane & 3;

    const int m0 = blockIdx.y * BM;
    const int n0 = blockIdx.x * BN;

    const int lr0 = tid >> 2;
    const int lr1 = lr0 + 64;
    const int lc4 = (tid & 3) * 4;

    const float* Ar0 = A + (size_t)(m0 + lr0) * lda + lc4;
    const float* Ar1 = A + (size_t)(m0 + lr1) * lda + lc4;
    const float* Wr0 = W + (size_t)(n0 + lr0) * ldw + lc4;
    const float* Wr1 = W + (size_t)(n0 + lr1) * ldw + lc4;

    float c[2][8][4];
#pragma unroll
    for (int i = 0; i < 2; i++)
#pragma unroll
        for (int j = 0; j < 8; j++)
#pragma unroll
            for (int r = 0; r < 4; r++) c[i][j][r] = 0.f;

    float4 av0 = *(const float4*)(Ar0);
    float4 av1 = *(const float4*)(Ar1);
    float4 wv0 = *(const float4*)(Wr0);
    float4 wv1 = *(const float4*)(Wr1);

#pragma unroll 1
    for (int k0 = 0; k0 < K; k0 += BK) {
        __syncthreads();
        {
            uint4 p;
            p.x = f2tf32(av0.x); p.y = f2tf32(av0.y);
            p.z = f2tf32(av0.z); p.w = f2tf32(av0.w);
            *(uint4*)&As[lr0][lc4] = p;
            p.x = f2tf32(av1.x); p.y = f2tf32(av1.y);
            p.z = f2tf32(av1.z); p.w = f2tf32(av1.w);
            *(uint4*)&As[lr1][lc4] = p;
            p.x = f2tf32(wv0.x); p.y = f2tf32(wv0.y);
            p.z = f2tf32(wv0.z); p.w = f2tf32(wv0.w);
            *(uint4*)&Bs[lr0][lc4] = p;
            p.x = f2tf32(wv1.x); p.y = f2tf32(wv1.y);
            p.z = f2tf32(wv1.z); p.w = f2tf32(wv1.w);
            *(uint4*)&Bs[lr1][lc4] = p;
        }
        __syncthreads();

        if (k0 + BK < K) {
            av0 = *(const float4*)(Ar0 + k0 + BK);
            av1 = *(const float4*)(Ar1 + k0 + BK);
            wv0 = *(const float4*)(Wr0 + k0 + BK);
            wv1 = *(const float4*)(Wr1 + k0 + BK);
        }

#pragma unroll
        for (int kk = 0; kk < 2; kk++) {
            const int kb = kk * 8;
            uint32_t a[2][4];
#pragma unroll
            for (int i = 0; i < 2; i++) {
                const int m = wm + i * 16 + g;
                a[i][0] = As[m][kb + tg];
                a[i][1] = As[m + 8][kb + tg];
                a[i][2] = As[m][kb + tg + 4];
                a[i][3] = As[m + 8][kb + tg + 4];
            }
#pragma unroll
            for (int j = 0; j < 8; j++) {
                const int n = wn + j * 8 + g;
                const uint32_t b0 = Bs[n][kb + tg];
                const uint32_t b1 = Bs[n][kb + tg + 4];
                mma_tf32(c[0][j], a[0], b0, b1);
                mma_tf32(c[1][j], a[1], b0, b1);
            }
        }
    }

#pragma unroll
    for (int i = 0; i < 2; i++) {
        const int mrow0 = m0 + wm + i * 16 + g;
#pragma unroll
        for (int j = 0; j < 8; j++) {
            const int ncol = n0 + wn + j * 8 + 2 * tg;
            *(float2*)&C[(size_t)mrow0 * ldc + ncol] =
                make_float2(c[i][j][0], c[i][j][1]);
            *(float2*)&C[(size_t)(mrow0 + 8) * ldc + ncol] =
                make_float2(c[i][j][2], c[i][j][3]);
        }
    }
}

// ---------------------------------------------------------------------------
// Stage 2+3 fused: conv1d+SiLU, x_proj GEMM; writes xs_t and z_t transposed.
// Block = 32 seq rows; 16 d-tiles of 64.  Side job: out_proj_w -> tf32.
// ---------------------------------------------------------------------------
__global__ void __launch_bounds__(256)
conv_xproj(const float* __restrict__ conv_w,
           const float* __restrict__ conv_b,
           const float* __restrict__ x_proj_w,
           const float* __restrict__ out_proj_w)
{
    __shared__ float sxs[32][68];
    __shared__ float sw[64][68];
    __shared__ float sz[32][68];

    const int tid = threadIdx.x;
    const int bl0 = blockIdx.x * 32;
    const int b   = bl0 >> 11;            // / 2048
    const int l0  = bl0 & 2047;
    const int tx = tid & 15;              // e / 4
    const int ty = tid >> 4;              // row / 2

    float acc[2][4];
#pragma unroll
    for (int i = 0; i < 2; i++)
#pragma unroll
        for (int j = 0; j < 4; j++) acc[i][j] = 0.f;

#pragma unroll 1
    for (int d0 = 0; d0 < DINNER; d0 += 64) {
        __syncthreads();
        // load W1 tile [64 e][64 d]
#pragma unroll
        for (int it = 0; it < 4; it++) {
            const int idx = tid + it * 256;
            const int e = idx >> 4, c4 = (idx & 15) * 4;
            *(float4*)&sw[e][c4] =
                *(const float4*)&x_proj_w[(size_t)e * DINNER + d0 + c4];
        }
        // conv+silu for 32 rows x 64 d; also stage z tile
#pragma unroll
        for (int it = 0; it < 8; it++) {
            const int idx = tid + it * 256;
            const int r = idx >> 6, dc = idx & 63;
            const int bl = bl0 + r;
            const int l = bl & (SEQLEN - 1);
            const int d = d0 + dc;
            float a = conv_b[d];
#pragma unroll
            for (int j = 0; j < DCONV; j++) {
                const int ls = l - (DCONV - 1) + j;
                if (ls >= 0)
                    a = fmaf(g_xz[(size_t)(bl - (DCONV - 1) + j) * (2 * DINNER) + d],
                             conv_w[d * DCONV + j], a);
            }
            sxs[r][dc] = a / (1.f + __expf(-a));     // SiLU
            sz[r][dc] = g_xz[(size_t)bl * (2 * DINNER) + DINNER + d];
        }
        __syncthreads();
        // transposed writes: xs_t[ch][l], z_t[ch][l]
        {
            const int dloc = tid >> 2;
            const int lq = (tid & 3) * 8;
            const size_t row = (size_t)(b * DINNER + d0 + dloc) * SEQLEN + l0 + lq;
            float4 v0, v1;
            v0.x = sxs[lq + 0][dloc]; v0.y = sxs[lq + 1][dloc];
            v0.z = sxs[lq + 2][dloc]; v0.w = sxs[lq + 3][dloc];
            v1.x = sxs[lq + 4][dloc]; v1.y = sxs[lq + 5][dloc];
            v1.z = sxs[lq + 6][dloc]; v1.w = sxs[lq + 7][dloc];
            *(float4*)&g_xst[row] = v0;
            *(float4*)&g_xst[row + 4] = v1;
            v0.x = sz[lq + 0][dloc]; v0.y = sz[lq + 1][dloc];
            v0.z = sz[lq + 2][dloc]; v0.w = sz[lq + 3][dloc];
            v1.x = sz[lq + 4][dloc]; v1.y = sz[lq + 5][dloc];
            v1.z = sz[lq + 6][dloc]; v1.w = sz[lq + 7][dloc];
            *(float4*)&g_zt[row] = v0;
            *(float4*)&g_zt[row + 4] = v1;
        }
        // accumulate xdbl[r][e] over this d-tile
#pragma unroll
        for (int kk = 0; kk < 64; kk++) {
            float ar[2], br[4];
#pragma unroll
            for (int i = 0; i < 2; i++) ar[i] = sxs[ty * 2 + i][kk];
#pragma unroll
            for (int j = 0; j < 4; j++) br[j] = sw[tx * 4 + j][kk];
#pragma unroll
            for (int i = 0; i < 2; i++)
#pragma unroll
                for (int j = 0; j < 4; j++)
                    acc[i][j] = fmaf(ar[i], br[j], acc[i][j]);
        }
    }

#pragma unroll
    for (int i = 0; i < 2; i++)
#pragma unroll
        for (int j = 0; j < 4; j++)
            g_xdbl[(size_t)(bl0 + ty * 2 + i) * 64 + tx * 4 + j] = acc[i][j];

    // side job: tf32-convert this block's slice of out_proj_w (4096 floats)
    const size_t base = (size_t)blockIdx.x * 4096;
#pragma unroll
    for (int it = 0; it < 4; it++) {
        const size_t off = base + (size_t)it * 1024 + tid * 4;
        float4 w4 = *(const float4*)&out_proj_w[off];
        uint4 p;
        p.x = f2tf32(w4.x); p.y = f2tf32(w4.y);
        p.z = f2tf32(w4.z); p.w = f2tf32(w4.w);
        *(uint4*)&g_w6tf[off] = p;
    }
}

// ---------------------------------------------------------------------------
// Stage 4: dt_proj + softplus -> delta_t[ch][l] (transposed write).
// ---------------------------------------------------------------------------
__global__ void __launch_bounds__(256)
gemm_nt4(const float* __restrict__ W, const float* __restrict__ bias)
{
    constexpr int BM = 64, BN = 64, BK = 16;
    constexpr int lda = 64, ldw = DTRANK, K = DTRANK;
    const float* A = g_xdbl;

    __shared__ float As[BK][BM];
    __shared__ float Bs[BK][BN];

    const int tid = threadIdx.x;
    const int m0 = blockIdx.y * BM;
    const int n0 = blockIdx.x * BN;
    const int tx = tid & 15;
    const int ty = tid >> 4;
    const int lrow = tid >> 2;
    const int lc4 = (tid & 3) * 4;

    float acc[4][4];
#pragma unroll
    for (int i = 0; i < 4; i++)
#pragma unroll
        for (int j = 0; j < 4; j++) acc[i][j] = 0.f;

    const float* Arow = A + (size_t)(m0 + lrow) * lda + lc4;
    const float* Wrow = W + (size_t)(n0 + lrow) * ldw + lc4;

#pragma unroll 1
    for (int k0 = 0; k0 < K; k0 += BK) {
        float4 av = *(const float4*)(Arow + k0);
        float4 wv = *(const float4*)(Wrow + k0);
        __syncthreads();
        As[lc4 + 0][lrow] = av.x; As[lc4 + 1][lrow] = av.y;
        As[lc4 + 2][lrow] = av.z; As[lc4 + 3][lrow] = av.w;
        Bs[lc4 + 0][lrow] = wv.x; Bs[lc4 + 1][lrow] = wv.y;
        Bs[lc4 + 2][lrow] = wv.z; Bs[lc4 + 3][lrow] = wv.w;
        __syncthreads();
#pragma unroll
        for (int kk = 0; kk < BK; kk++) {
            float4 a4 = *(const float4*)&As[kk][ty * 4];
            float4 b4 = *(const float4*)&Bs[kk][tx * 4];
            float ar[4] = {a4.x, a4.y, a4.z, a4.w};
            float br[4] = {b4.x, b4.y, b4.z, b4.w};
#pragma unroll
            for (int i = 0; i < 4; i++)
#pragma unroll
                for (int j = 0; j < 4; j++)
                    acc[i][j] = fmaf(ar[i], br[j], acc[i][j]);
        }
    }

    // transposed epilogue: delta_t[(b*DINNER + n)][l], l = m within batch
    const int b = m0 >> 11;
    const int lb = (m0 & 2047) + ty * 4;
#pragma unroll
    for (int j = 0; j < 4; j++) {
        const int n = n0 + tx * 4 + j;
        float sp[4];
#pragma unroll
        for (int i = 0; i < 4; i++) {
            float v = acc[i][j] + bias[n];
            sp[i] = (v > 20.f) ? v : log1pf(__expf(v));
        }
        *(float4*)&g_deltat[(size_t)(b * DINNER + n) * SEQLEN + lb] =
            make_float4(sp[0], sp[1], sp[2], sp[3]);
    }
}

// ---------------------------------------------------------------------------
// Stage 5: selective scan, cp.async 2-stage smem pipeline.
// 8 channels/block (16 lanes each).  CH=32 steps per chunk.
// Streams: delta_t/xs_t/z_t (contiguous per channel), B,C from g_xdbl rows.
// y gathered in smem -> 32B-sector row-major stores (tf32-rounded).
// ---------------------------------------------------------------------------
__global__ void __launch_bounds__(128)
scan_kernel(const float* __restrict__ A_log,
            const float* __restrict__ D_param)
{
    constexpr int CH = 32, NCHK = SEQLEN / CH, SP = CH + 4;
    __shared__ __align__(16) float s_dt[2][8][SP];
    __shared__ __align__(16) float s_u [2][8][SP];
    __shared__ __align__(16) float s_z [2][8][SP];
    __shared__ __align__(16) float s_bc[2][CH][32];
    __shared__ float s_y[CH][8];

    const int tid = threadIdx.x;
    const int ch  = tid >> 4;                 // 0..7
    const int n   = tid & 15;                 // state
    const int c0  = blockIdx.x * 8;           // channel base = b*1024+d
    const int b   = c0 >> 10;
    const int d   = (c0 + ch) & (DINNER - 1);

    const float A_dn = -__expf(A_log[d * DSTATE + n]);
    const float Dd = D_param[d];
    const float* xd = g_xdbl + (size_t)b * SEQLEN * 64;

    auto fill = [&](int s, int c) {
        const int l0 = c * CH;
        // dt/u/z: 3 streams x 8 ch x 8 x 16B
#pragma unroll
        for (int it = 0; it < 2; it++) {
            const int id = tid + it * 128;
            if (id < 192) {
                const int st = id >> 6;
                const int r = id & 63;
                const int cc = r >> 3, q = (r & 7) * 4;
                const size_t src = (size_t)(c0 + cc) * SEQLEN + l0 + q;
                if (st == 0)
                    cp16((uint32_t)__cvta_generic_to_shared(&s_dt[s][cc][q]),
                         g_deltat + src);
                else if (st == 1)
                    cp16((uint32_t)__cvta_generic_to_shared(&s_u[s][cc][q]),
                         g_xst + src);
                else
                    cp16((uint32_t)__cvta_generic_to_shared(&s_z[s][cc][q]),
                         g_zt + src);
            }
        }
        // B,C: CH rows x 128B  (cols 32..63 of xdbl row)
#pragma unroll
        for (int it = 0; it < 2; it++) {
            const int id = tid + it * 128;
            const int j = id >> 3, q = (id & 7) * 4;
            cp16((uint32_t)__cvta_generic_to_shared(&s_bc[s][j][q]),
                 xd + (size_t)(l0 + j) * 64 + 32 + q);
        }
    };

    fill(0, 0); asm volatile("cp.async.commit_group;\n" ::);
    fill(1, 1); asm volatile("cp.async.commit_group;\n" ::);

    float h = 0.f;
#pragma unroll 1
    for (int c = 0; c < NCHK; c++) {
        const int s = c & 1;
        if (c < NCHK - 1) asm volatile("cp.async.wait_group 1;\n" ::);
        else              asm volatile("cp.async.wait_group 0;\n" ::);
        __syncthreads();
#pragma unroll
        for (int j = 0; j < CH; j++) {
            const float dt_c = s_dt[s][ch][j];
            const float u_c  = s_u[s][ch][j];
            const float dA = __expf(dt_c * A_dn);
            const float Bn = s_bc[s][j][n];
            const float Cn = s_bc[s][j][16 + n];
            h = fmaf(dA, h, dt_c * u_c * Bn);
            float p = h * Cn;
            p += __shfl_xor_sync(0xffffffffu, p, 8, 16);
            p += __shfl_xor_sync(0xffffffffu, p, 4, 16);
            p += __shfl_xor_sync(0xffffffffu, p, 2, 16);
            p += __shfl_xor_sync(0xffffffffu, p, 1, 16);
            if (n == 0) {
                const float z = s_z[s][ch][j];
                const float sz = z / (1.f + __expf(-z));
                s_y[j][ch] = __uint_as_float(f2tf32((p + u_c * Dd) * sz));
            }
        }
        __syncthreads();
        // store y chunk [CH l][8 d] -> g_y row-major
        const int l0 = c * CH;
#pragma unroll
        for (int it = 0; it < 2; it++) {
            const int id = tid + it * 128;
            const int j = id >> 3, cc = id & 7;
            g_y[(size_t)(b * SEQLEN + l0 + j) * DINNER + (c0 & (DINNER - 1)) + cc] =
                s_y[j][cc];
        }
        if (c + 2 < NCHK) { fill(s, c + 2); asm volatile("cp.async.commit_group;\n" ::); }
    }
}

// ---------------------------------------------------------------------------
// Stage 6: out_proj, tf32 mma, cp.async 2-stage pipeline (inputs pre-tf32).
// ---------------------------------------------------------------------------
__global__ void __launch_bounds__(256)
gemm_mma6(float* __restrict__ C)
{
    constexpr int BM = 128, BN = 128, BK = 16, SST = BK + 4;
    constexpr int lda = DINNER, ldw = DINNER, ldc = DMODEL;
    constexpr int NT = DINNER / BK;

    __shared__ __align__(16) uint32_t As[2][BM][SST];
    __shared__ __align__(16) uint32_t Bs[2][BN][SST];

    const int tid = threadIdx.x;
    const int lane = tid & 31;
    const int wid = tid >> 5;
    const int wm = (wid & 3) * 32;
    const int wn = (wid >> 2) * 64;
    const int g  = lane >> 2;
    const int tg = lane & 3;

    const int m0 = blockIdx.y * BM;
    const int n0 = blockIdx.x * BN;

    const int lr0 = tid >> 2;
    const int lr1 = lr0 + 64;
    const int lc4 = (tid & 3) * 4;

    const float* Ar0 = g_y + (size_t)(m0 + lr0) * lda + lc4;
    const float* Ar1 = g_y + (size_t)(m0 + lr1) * lda + lc4;
    const uint32_t* Wr0 = g_w6tf + (size_t)(n0 + lr0) * ldw + lc4;
    const uint32_t* Wr1 = g_w6tf + (size_t)(n0 + lr1) * ldw + lc4;

    uint32_t sA0 = (uint32_t)__cvta_generic_to_shared(&As[0][lr0][lc4]);
    uint32_t sA1 = (uint32_t)__cvta_generic_to_shared(&As[0][lr1][lc4]);
    uint32_t sB0 = (uint32_t)__cvta_generic_to_shared(&Bs[0][lr0][lc4]);
    uint32_t sB1 = (uint32_t)__cvta_generic_to_shared(&Bs[0][lr1][lc4]);
    constexpr uint32_t STAGE_A = sizeof(uint32_t) * BM * SST;
    constexpr uint32_t STAGE_B = sizeof(uint32_t) * BN * SST;

    float c[2][8][4];
#pragma unroll
    for (int i = 0; i < 2; i++)
#pragma unroll
        for (int j = 0; j < 8; j++)
#pragma unroll
            for (int r = 0; r < 4; r++) c[i][j][r] = 0.f;

    cp16(sA0, Ar0); cp16(sA1, Ar1);
    cp16(sB0, Wr0); cp16(sB1, Wr1);
    asm volatile("cp.async.commit_group;\n" ::);

#pragma unroll 1
    for (int kt = 0; kt < NT; kt++) {
        const int s = kt & 1;
        if (kt + 1 < NT) {
            const int k = (kt + 1) * BK;
            const uint32_t so = (uint32_t)((kt + 1) & 1);
            cp16(sA0 + so * STAGE_A, Ar0 + k);
            cp16(sA1 + so * STAGE_A, Ar1 + k);
            cp16(sB0 + so * STAGE_B, Wr0 + k);
            cp16(sB1 + so * STAGE_B, Wr1 + k);
            asm volatile("cp.async.commit_group;\n" ::);
            asm volatile("cp.async.wait_group 1;\n" ::);
        } else {
            asm volatile("cp.async.wait_group 0;\n" ::);
        }
        __syncthreads();

#pragma unroll
        for (int kk = 0; kk < 2; kk++) {
            const int kb = kk * 8;
            uint32_t a[2][4];
#pragma unroll
            for (int i = 0; i < 2; i++) {
                const int m = wm + i * 16 + g;
                a[i][0] = As[s][m][kb + tg];
                a[i][1] = As[s][m + 8][kb + tg];
                a[i][2] = As[s][m][kb + tg + 4];
                a[i][3] = As[s][m + 8][kb + tg + 4];
            }
#pragma unroll
            for (int j = 0; j < 8; j++) {
                const int n = wn + j * 8 + g;
                const uint32_t b0 = Bs[s][n][kb + tg];
                const uint32_t b1 = Bs[s][n][kb + tg + 4];
                mma_tf32(c[0][j], a[0], b0, b1);
                mma_tf32(c[1][j], a[1], b0, b1);
            }
        }
        __syncthreads();
    }

#pragma unroll
    for (int i = 0; i < 2; i++) {
        const int mrow0 = m0 + wm + i * 16 + g;
#pragma unroll
        for (int j = 0; j < 8; j++) {
            const int ncol = n0 + wn + j * 8 + 2 * tg;
            *(float2*)&C[(size_t)mrow0 * ldc + ncol] =
                make_float2(c[i][j][0], c[i][j][1]);
            *(float2*)&C[(size_t)(mrow0 + 8) * ldc + ncol] =
                make_float2(c[i][j][2], c[i][j][3]);
        }
    }
}

// ---------------------------------------------------------------------------
extern "C" void kernel_launch(void* const* d_in, const int* in_sizes, int n_in,
                              void* d_out, int out_size)
{
    const float* x          = (const float*)d_in[0];
    const float* in_proj_w  = (const float*)d_in[1];
    const float* conv_w     = (const float*)d_in[2];
    const float* conv_b     = (const float*)d_in[3];
    const float* x_proj_w   = (const float*)d_in[4];
    const float* dt_proj_w  = (const float*)d_in[5];
    const float* dt_proj_b  = (const float*)d_in[6];
    const float* A_log      = (const float*)d_in[7];
    const float* D_param    = (const float*)d_in[8];
    const float* out_proj_w = (const float*)d_in[9];
    float* out = (float*)d_out;

    // 1) in_proj (tf32 mma) -> g_xz [4096,2048]
    gemm_mma1<<<dim3(2 * DINNER / 128, MROWS / 128), 256>>>(x, in_proj_w);

    // 2+3) conv+silu fused with x_proj -> g_xst, g_zt, g_xdbl (+ w6 cvt)
    conv_xproj<<<MROWS / 32, 256>>>(conv_w, conv_b, x_proj_w, out_proj_w);

    // 4) dt_proj + softplus -> g_deltat [2048 ch][2048 l]
    gemm_nt4<<<dim3(DINNER / 64, MROWS / 64), 256>>>(dt_proj_w, dt_proj_b);

    // 5) selective scan (cp.async pipelined) -> g_y (tf32-rounded)
    scan_kernel<<<NCHAN / 8, 128>>>(A_log, D_param);

    // 6) out_proj (tf32 mma, cp.async) -> out [4096,512]
    gemm_mma6<<<dim3(DMODEL / 128, MROWS / 128), 256>>>(out);
}

// round 7
// speedup vs baseline: 2.8219x; 1.5479x over previous
#include <cuda_runtime.h>
#include <cuda_bf16.h>
#include <cstdint>

// ---------------------------------------------------------------------------
// Mamba block forward.  B=2, L=2048, d_model=512, d_inner=1024, d_state=16,
// dt_rank=32, d_conv=4.
// Launches: 1 gemm_mma1    in_proj (tf32 mma)
//           2 conv_xproj   conv+silu + x_proj fused; xs_t/z_t transposed
//           3 gemm_nt4     dt_proj + softplus -> delta_t (transposed)
//           4 scan_phaseA  per-chunk local scan summaries (h_end, decay)
//           5 scan_phaseB  chunk-state composition -> h0 per chunk
//           6 scan_phaseC  per-chunk full scan from h0 -> y
//           7 gemm_mma6    out_proj (tf32 mma, cp.async)
// ---------------------------------------------------------------------------

#define BATCH    2
#define SEQLEN   2048
#define DMODEL   512
#define DINNER   1024
#define DSTATE   16
#define DTRANK   32
#define DCONV    4
#define MROWS    (BATCH * SEQLEN)        // 4096
#define NCHAN    (BATCH * DINNER)        // 2048 scan channels
#define TCHUNK   16                      // scan chunks along L
#define CLEN     (SEQLEN / TCHUNK)       // 128 steps per chunk

// Scratch (device-global; no runtime allocation allowed)
__device__ float g_xz[(size_t)MROWS * 2 * DINNER];    // [4096, 2048]  xs | z
__device__ float g_xst[(size_t)NCHAN * SEQLEN];       // xs transposed [ch][l]
__device__ float g_zt[(size_t)NCHAN * SEQLEN];        // z transposed [ch][l]
__device__ float g_xdbl[(size_t)MROWS * 64];          // [4096, 64]
__device__ float g_deltat[(size_t)NCHAN * SEQLEN];    // delta transposed [ch][l]
__device__ float g_y[(size_t)MROWS * DINNER];         // scan output (tf32-rounded)
__device__ uint32_t g_w6tf[(size_t)DMODEL * DINNER];  // out_proj_w in tf32
__device__ float g_hend[(size_t)TCHUNK * NCHAN * DSTATE];
__device__ float g_decay[(size_t)TCHUNK * NCHAN * DSTATE];
__device__ float g_h0[(size_t)TCHUNK * NCHAN * DSTATE];

// ---------------------------------------------------------------------------
__device__ __forceinline__ uint32_t f2tf32(float f) {
    uint32_t r;
    asm("cvt.rna.tf32.f32 %0, %1;" : "=r"(r) : "f"(f));
    return r;
}

__device__ __forceinline__ void mma_tf32(float c[4], const uint32_t a[4],
                                         uint32_t b0, uint32_t b1) {
    asm volatile(
        "mma.sync.aligned.m16n8k8.row.col.f32.tf32.tf32.f32 "
        "{%0,%1,%2,%3}, {%4,%5,%6,%7}, {%8,%9}, {%0,%1,%2,%3};"
        : "+f"(c[0]), "+f"(c[1]), "+f"(c[2]), "+f"(c[3])
        : "r"(a[0]), "r"(a[1]), "r"(a[2]), "r"(a[3]), "r"(b0), "r"(b1));
}

__device__ __forceinline__ void cp16(uint32_t dst_smem, const void* src) {
    asm volatile("cp.async.cg.shared.global [%0], [%1], 16;\n"
                 :: "r"(dst_smem), "l"(src));
}

// ---------------------------------------------------------------------------
// Stage 1: in_proj, tf32 mma.  C[m,n] = sum_k x[m,k] W[n,k]; 4096x2048x512.
// ---------------------------------------------------------------------------
__global__ void __launch_bounds__(256)
gemm_mma1(const float* __restrict__ A, const float* __restrict__ W)
{
    constexpr int BM = 128, BN = 128, BK = 16, SST = BK + 4;
    constexpr int lda = DMODEL, ldw = DMODEL, ldc = 2 * DINNER, K = DMODEL;
    float* C = g_xz;

    __shared__ __align__(16) uint32_t As[BM][SST];
    __shared__ __align__(16) uint32_t Bs[BN][SST];

    const int tid = threadIdx.x;
    const int lane = tid & 31;
    const int wid = tid >> 5;
    const int wm = (wid & 3) * 32;
    const int wn = (wid >> 2) * 64;
    const int g  = lane >> 2;
    const int tg = lane & 3;

    const int m0 = blockIdx.y * BM;
    const int n0 = blockIdx.x * BN;

    const int lr0 = tid >> 2;
    const int lr1 = lr0 + 64;
    const int lc4 = (tid & 3) * 4;

    const float* Ar0 = A + (size_t)(m0 + lr0) * lda + lc4;
    const float* Ar1 = A + (size_t)(m0 + lr1) * lda + lc4;
    const float* Wr0 = W + (size_t)(n0 + lr0) * ldw + lc4;
    const float* Wr1 = W + (size_t)(n0 + lr1) * ldw + lc4;

    float c[2][8][4];
#pragma unroll
    for (int i = 0; i < 2; i++)
#pragma unroll
        for (int j = 0; j < 8; j++)
#pragma unroll
            for (int r = 0; r < 4; r++) c[i][j][r] = 0.f;

    float4 av0 = *(const float4*)(Ar0);
    float4 av1 = *(const float4*)(Ar1);
    float4 wv0 = *(const float4*)(Wr0);
    float4 wv1 = *(const float4*)(Wr1);

#pragma unroll 1
    for (int k0 = 0; k0 < K; k0 += BK) {
        __syncthreads();
        {
            uint4 p;
            p.x = f2tf32(av0.x); p.y = f2tf32(av0.y);
            p.z = f2tf32(av0.z); p.w = f2tf32(av0.w);
            *(uint4*)&As[lr0][lc4] = p;
            p.x = f2tf32(av1.x); p.y = f2tf32(av1.y);
            p.z = f2tf32(av1.z); p.w = f2tf32(av1.w);
            *(uint4*)&As[lr1][lc4] = p;
            p.x = f2tf32(wv0.x); p.y = f2tf32(wv0.y);
            p.z = f2tf32(wv0.z); p.w = f2tf32(wv0.w);
            *(uint4*)&Bs[lr0][lc4] = p;
            p.x = f2tf32(wv1.x); p.y = f2tf32(wv1.y);
            p.z = f2tf32(wv1.z); p.w = f2tf32(wv1.w);
            *(uint4*)&Bs[lr1][lc4] = p;
        }
        __syncthreads();

        if (k0 + BK < K) {
            av0 = *(const float4*)(Ar0 + k0 + BK);
            av1 = *(const float4*)(Ar1 + k0 + BK);
            wv0 = *(const float4*)(Wr0 + k0 + BK);
            wv1 = *(const float4*)(Wr1 + k0 + BK);
        }

#pragma unroll
        for (int kk = 0; kk < 2; kk++) {
            const int kb = kk * 8;
            uint32_t a[2][4];
#pragma unroll
            for (int i = 0; i < 2; i++) {
                const int m = wm + i * 16 + g;
                a[i][0] = As[m][kb + tg];
                a[i][1] = As[m + 8][kb + tg];
                a[i][2] = As[m][kb + tg + 4];
                a[i][3] = As[m + 8][kb + tg + 4];
            }
#pragma unroll
            for (int j = 0; j < 8; j++) {
                const int n = wn + j * 8 + g;
                const uint32_t b0 = Bs[n][kb + tg];
                const uint32_t b1 = Bs[n][kb + tg + 4];
                mma_tf32(c[0][j], a[0], b0, b1);
                mma_tf32(c[1][j], a[1], b0, b1);
            }
        }
    }

#pragma unroll
    for (int i = 0; i < 2; i++) {
        const int mrow0 = m0 + wm + i * 16 + g;
#pragma unroll
        for (int j = 0; j < 8; j++) {
            const int ncol = n0 + wn + j * 8 + 2 * tg;
            *(float2*)&C[(size_t)mrow0 * ldc + ncol] =
                make_float2(c[i][j][0], c[i][j][1]);
            *(float2*)&C[(size_t)(mrow0 + 8) * ldc + ncol] =
                make_float2(c[i][j][2], c[i][j][3]);
        }
    }
}

// ---------------------------------------------------------------------------
// Stage 2+3 fused: conv1d+SiLU, x_proj GEMM; writes xs_t and z_t transposed.
// ---------------------------------------------------------------------------
__global__ void __launch_bounds__(256)
conv_xproj(const float* __restrict__ conv_w,
           const float* __restrict__ conv_b,
           const float* __restrict__ x_proj_w,
           const float* __restrict__ out_proj_w)
{
    __shared__ float sxs[32][68];
    __shared__ float sw[64][68];
    __shared__ float sz[32][68];

    const int tid = threadIdx.x;
    const int bl0 = blockIdx.x * 32;
    const int b   = bl0 >> 11;
    const int l0  = bl0 & 2047;
    const int tx = tid & 15;
    const int ty = tid >> 4;

    float acc[2][4];
#pragma unroll
    for (int i = 0; i < 2; i++)
#pragma unroll
        for (int j = 0; j < 4; j++) acc[i][j] = 0.f;

#pragma unroll 1
    for (int d0 = 0; d0 < DINNER; d0 += 64) {
        __syncthreads();
#pragma unroll
        for (int it = 0; it < 4; it++) {
            const int idx = tid + it * 256;
            const int e = idx >> 4, c4 = (idx & 15) * 4;
            *(float4*)&sw[e][c4] =
                *(const float4*)&x_proj_w[(size_t)e * DINNER + d0 + c4];
        }
#pragma unroll
        for (int it = 0; it < 8; it++) {
            const int idx = tid + it * 256;
            const int r = idx >> 6, dc = idx & 63;
            const int bl = bl0 + r;
            const int l = bl & (SEQLEN - 1);
            const int d = d0 + dc;
            float a = conv_b[d];
#pragma unroll
            for (int j = 0; j < DCONV; j++) {
                const int ls = l - (DCONV - 1) + j;
                if (ls >= 0)
                    a = fmaf(g_xz[(size_t)(bl - (DCONV - 1) + j) * (2 * DINNER) + d],
                             conv_w[d * DCONV + j], a);
            }
            sxs[r][dc] = a / (1.f + __expf(-a));     // SiLU
            sz[r][dc] = g_xz[(size_t)bl * (2 * DINNER) + DINNER + d];
        }
        __syncthreads();
        {
            const int dloc = tid >> 2;
            const int lq = (tid & 3) * 8;
            const size_t row = (size_t)(b * DINNER + d0 + dloc) * SEQLEN + l0 + lq;
            float4 v0, v1;
            v0.x = sxs[lq + 0][dloc]; v0.y = sxs[lq + 1][dloc];
            v0.z = sxs[lq + 2][dloc]; v0.w = sxs[lq + 3][dloc];
            v1.x = sxs[lq + 4][dloc]; v1.y = sxs[lq + 5][dloc];
            v1.z = sxs[lq + 6][dloc]; v1.w = sxs[lq + 7][dloc];
            *(float4*)&g_xst[row] = v0;
            *(float4*)&g_xst[row + 4] = v1;
            v0.x = sz[lq + 0][dloc]; v0.y = sz[lq + 1][dloc];
            v0.z = sz[lq + 2][dloc]; v0.w = sz[lq + 3][dloc];
            v1.x = sz[lq + 4][dloc]; v1.y = sz[lq + 5][dloc];
            v1.z = sz[lq + 6][dloc]; v1.w = sz[lq + 7][dloc];
            *(float4*)&g_zt[row] = v0;
            *(float4*)&g_zt[row + 4] = v1;
        }
#pragma unroll
        for (int kk = 0; kk < 64; kk++) {
            float ar[2], br[4];
#pragma unroll
            for (int i = 0; i < 2; i++) ar[i] = sxs[ty * 2 + i][kk];
#pragma unroll
            for (int j = 0; j < 4; j++) br[j] = sw[tx * 4 + j][kk];
#pragma unroll
            for (int i = 0; i < 2; i++)
#pragma unroll
                for (int j = 0; j < 4; j++)
                    acc[i][j] = fmaf(ar[i], br[j], acc[i][j]);
        }
    }

#pragma unroll
    for (int i = 0; i < 2; i++)
#pragma unroll
        for (int j = 0; j < 4; j++)
            g_xdbl[(size_t)(bl0 + ty * 2 + i) * 64 + tx * 4 + j] = acc[i][j];

    const size_t base = (size_t)blockIdx.x * 4096;
#pragma unroll
    for (int it = 0; it < 4; it++) {
        const size_t off = base + (size_t)it * 1024 + tid * 4;
        float4 w4 = *(const float4*)&out_proj_w[off];
        uint4 p;
        p.x = f2tf32(w4.x); p.y = f2tf32(w4.y);
        p.z = f2tf32(w4.z); p.w = f2tf32(w4.w);
        *(uint4*)&g_w6tf[off] = p;
    }
}

// ---------------------------------------------------------------------------
// Stage 4: dt_proj + softplus -> delta_t[ch][l] (transposed write).
// ---------------------------------------------------------------------------
__global__ void __launch_bounds__(256)
gemm_nt4(const float* __restrict__ W, const float* __restrict__ bias)
{
    constexpr int BM = 64, BN = 64, BK = 16;
    constexpr int lda = 64, ldw = DTRANK, K = DTRANK;
    const float* A = g_xdbl;

    __shared__ float As[BK][BM];
    __shared__ float Bs[BK][BN];

    const int tid = threadIdx.x;
    const int m0 = blockIdx.y * BM;
    const int n0 = blockIdx.x * BN;
    const int tx = tid & 15;
    const int ty = tid >> 4;
    const int lrow = tid >> 2;
    const int lc4 = (tid & 3) * 4;

    float acc[4][4];
#pragma unroll
    for (int i = 0; i < 4; i++)
#pragma unroll
        for (int j = 0; j < 4; j++) acc[i][j] = 0.f;

    const float* Arow = A + (size_t)(m0 + lrow) * lda + lc4;
    const float* Wrow = W + (size_t)(n0 + lrow) * ldw + lc4;

#pragma unroll 1
    for (int k0 = 0; k0 < K; k0 += BK) {
        float4 av = *(const float4*)(Arow + k0);
        float4 wv = *(const float4*)(Wrow + k0);
        __syncthreads();
        As[lc4 + 0][lrow] = av.x; As[lc4 + 1][lrow] = av.y;
        As[lc4 + 2][lrow] = av.z; As[lc4 + 3][lrow] = av.w;
        Bs[lc4 + 0][lrow] = wv.x; Bs[lc4 + 1][lrow] = wv.y;
        Bs[lc4 + 2][lrow] = wv.z; Bs[lc4 + 3][lrow] = wv.w;
        __syncthreads();
#pragma unroll
        for (int kk = 0; kk < BK; kk++) {
            float4 a4 = *(const float4*)&As[kk][ty * 4];
            float4 b4 = *(const float4*)&Bs[kk][tx * 4];
            float ar[4] = {a4.x, a4.y, a4.z, a4.w};
            float br[4] = {b4.x, b4.y, b4.z, b4.w};
#pragma unroll
            for (int i = 0; i < 4; i++)
#pragma unroll
                for (int j = 0; j < 4; j++)
                    acc[i][j] = fmaf(ar[i], br[j], acc[i][j]);
        }
    }

    const int b = m0 >> 11;
    const int lb = (m0 & 2047) + ty * 4;
#pragma unroll
    for (int j = 0; j < 4; j++) {
        const int n = n0 + tx * 4 + j;
        float sp[4];
#pragma unroll
        for (int i = 0; i < 4; i++) {
            float v = acc[i][j] + bias[n];
            sp[i] = (v > 20.f) ? v : log1pf(__expf(v));
        }
        *(float4*)&g_deltat[(size_t)(b * DINNER + n) * SEQLEN + lb] =
            make_float4(sp[0], sp[1], sp[2], sp[3]);
    }
}

// ---------------------------------------------------------------------------
// Scan phase A: per-chunk local scan (h from 0) -> h_end, decay per (ch,n).
// Grid (NCHAN/8, TCHUNK), 128 threads = 8 channels x 16 state lanes.
// ---------------------------------------------------------------------------
__global__ void __launch_bounds__(128)
scan_phaseA(const float* __restrict__ A_log)
{
    const int tid = threadIdx.x;
    const int ch = tid >> 4;
    const int n  = tid & 15;
    const int chg = blockIdx.x * 8 + ch;
    const int t = blockIdx.y;
    const int b = chg >> 10;
    const int d = chg & (DINNER - 1);

    const float A_dn = -__expf(A_log[d * DSTATE + n]);
    const float* dl = g_deltat + (size_t)chg * SEQLEN + t * CLEN;
    const float* us = g_xst    + (size_t)chg * SEQLEN + t * CLEN;
    const float* xd = g_xdbl + ((size_t)b * SEQLEN + t * CLEN) * 64 + 32 + n;

    float h = 0.f, pref = 1.f;
#pragma unroll 4
    for (int l = 0; l < CLEN; l++) {
        const float dt = dl[l];
        const float u  = us[l];
        const float Bn = xd[(size_t)l * 64];
        const float dA = __expf(dt * A_dn);
        h = fmaf(dA, h, dt * u * Bn);
        pref *= dA;
    }
    const size_t o = ((size_t)t * NCHAN + chg) * DSTATE + n;
    g_hend[o] = h;
    g_decay[o] = pref;
}

// ---------------------------------------------------------------------------
// Scan phase B: compose chunk states serially over T chunks.
// 32768 threads, one per (ch, n).
// ---------------------------------------------------------------------------
__global__ void __launch_bounds__(256)
scan_phaseB()
{
    const int id = blockIdx.x * 256 + threadIdx.x;   // 0..NCHAN*DSTATE-1
    float h = 0.f;
#pragma unroll
    for (int t = 0; t < TCHUNK; t++) {
        const size_t o = (size_t)t * NCHAN * DSTATE + id;
        g_h0[o] = h;
        h = g_decay[o] * h + g_hend[o];
    }
}

// ---------------------------------------------------------------------------
// Scan phase C: full scan per chunk starting from h0; cp.async pipelined.
// Grid (NCHAN/8, TCHUNK).  CH=32 steps per smem stage; 4 stages per chunk.
// ---------------------------------------------------------------------------
__global__ void __launch_bounds__(128)
scan_phaseC(const float* __restrict__ A_log,
            const float* __restrict__ D_param)
{
    constexpr int CH = 32, NCHK = CLEN / CH, SP = CH + 4;
    __shared__ __align__(16) float s_dt[2][8][SP];
    __shared__ __align__(16) float s_u [2][8][SP];
    __shared__ __align__(16) float s_z [2][8][SP];
    __shared__ __align__(16) float s_bc[2][CH][32];
    __shared__ float s_y[CH][8];

    const int tid = threadIdx.x;
    const int ch  = tid >> 4;
    const int n   = tid & 15;
    const int c0  = blockIdx.x * 8;
    const int t   = blockIdx.y;
    const int b   = c0 >> 10;
    const int d   = (c0 + ch) & (DINNER - 1);
    const int lbase = t * CLEN;

    const float A_dn = -__expf(A_log[d * DSTATE + n]);
    const float Dd = D_param[d];
    const float* xd = g_xdbl + (size_t)b * SEQLEN * 64;

    auto fill = [&](int s, int c) {
        const int l0 = lbase + c * CH;
#pragma unroll
        for (int it = 0; it < 2; it++) {
            const int id = tid + it * 128;
            if (id < 192) {
                const int st = id >> 6;
                const int r = id & 63;
                const int cc = r >> 3, q = (r & 7) * 4;
                const size_t src = (size_t)(c0 + cc) * SEQLEN + l0 + q;
                if (st == 0)
                    cp16((uint32_t)__cvta_generic_to_shared(&s_dt[s][cc][q]),
                         g_deltat + src);
                else if (st == 1)
                    cp16((uint32_t)__cvta_generic_to_shared(&s_u[s][cc][q]),
                         g_xst + src);
                else
                    cp16((uint32_t)__cvta_generic_to_shared(&s_z[s][cc][q]),
                         g_zt + src);
            }
        }
#pragma unroll
        for (int it = 0; it < 2; it++) {
            const int id = tid + it * 128;
            const int j = id >> 3, q = (id & 7) * 4;
            cp16((uint32_t)__cvta_generic_to_shared(&s_bc[s][j][q]),
                 xd + (size_t)(l0 + j) * 64 + 32 + q);
        }
    };

    fill(0, 0); asm volatile("cp.async.commit_group;\n" ::);
    fill(1, 1); asm volatile("cp.async.commit_group;\n" ::);

    float h = g_h0[(size_t)t * NCHAN * DSTATE + (size_t)(c0 + ch) * DSTATE + n];
#pragma unroll 1
    for (int c = 0; c < NCHK; c++) {
        const int s = c & 1;
        if (c < NCHK - 1) asm volatile("cp.async.wait_group 1;\n" ::);
        else              asm volatile("cp.async.wait_group 0;\n" ::);
        __syncthreads();
#pragma unroll
        for (int j = 0; j < CH; j++) {
            const float dt_c = s_dt[s][ch][j];
            const float u_c  = s_u[s][ch][j];
            const float dA = __expf(dt_c * A_dn);
            const float Bn = s_bc[s][j][n];
            const float Cn = s_bc[s][j][16 + n];
            h = fmaf(dA, h, dt_c * u_c * Bn);
            float p = h * Cn;
            p += __shfl_xor_sync(0xffffffffu, p, 8, 16);
            p += __shfl_xor_sync(0xffffffffu, p, 4, 16);
            p += __shfl_xor_sync(0xffffffffu, p, 2, 16);
            p += __shfl_xor_sync(0xffffffffu, p, 1, 16);
            if (n == 0) {
                const float z = s_z[s][ch][j];
                const float sz = z / (1.f + __expf(-z));
                s_y[j][ch] = __uint_as_float(f2tf32((p + u_c * Dd) * sz));
            }
        }
        __syncthreads();
        const int l0 = lbase + c * CH;
#pragma unroll
        for (int it = 0; it < 2; it++) {
            const int id = tid + it * 128;
            const int j = id >> 3, cc = id & 7;
            g_y[(size_t)(b * SEQLEN + l0 + j) * DINNER + (c0 & (DINNER - 1)) + cc] =
                s_y[j][cc];
        }
        if (c + 2 < NCHK) { fill(s, c + 2); asm volatile("cp.async.commit_group;\n" ::); }
    }
}

// ---------------------------------------------------------------------------
// Stage 6: out_proj, tf32 mma, cp.async 2-stage pipeline (inputs pre-tf32).
// ---------------------------------------------------------------------------
__global__ void __launch_bounds__(256)
gemm_mma6(float* __restrict__ C)
{
    constexpr int BM = 128, BN = 128, BK = 16, SST = BK + 4;
    constexpr int lda = DINNER, ldw = DINNER, ldc = DMODEL;
    constexpr int NT = DINNER / BK;

    __shared__ __align__(16) uint32_t As[2][BM][SST];
    __shared__ __align__(16) uint32_t Bs[2][BN][SST];

    const int tid = threadIdx.x;
    const int lane = tid & 31;
    const int wid = tid >> 5;
    const int wm = (wid & 3) * 32;
    const int wn = (wid >> 2) * 64;
    const int g  = lane >> 2;
    const int tg = lane & 3;

    const int m0 = blockIdx.y * BM;
    const int n0 = blockIdx.x * BN;

    const int lr0 = tid >> 2;
    const int lr1 = lr0 + 64;
    const int lc4 = (tid & 3) * 4;

    const float* Ar0 = g_y + (size_t)(m0 + lr0) * lda + lc4;
    const float* Ar1 = g_y + (size_t)(m0 + lr1) * lda + lc4;
    const uint32_t* Wr0 = g_w6tf + (size_t)(n0 + lr0) * ldw + lc4;
    const uint32_t* Wr1 = g_w6tf + (size_t)(n0 + lr1) * ldw + lc4;

    uint32_t sA0 = (uint32_t)__cvta_generic_to_shared(&As[0][lr0][lc4]);
    uint32_t sA1 = (uint32_t)__cvta_generic_to_shared(&As[0][lr1][lc4]);
    uint32_t sB0 = (uint32_t)__cvta_generic_to_shared(&Bs[0][lr0][lc4]);
    uint32_t sB1 = (uint32_t)__cvta_generic_to_shared(&Bs[0][lr1][lc4]);
    constexpr uint32_t STAGE_A = sizeof(uint32_t) * BM * SST;
    constexpr uint32_t STAGE_B = sizeof(uint32_t) * BN * SST;

    float c[2][8][4];
#pragma unroll
    for (int i = 0; i < 2; i++)
#pragma unroll
        for (int j = 0; j < 8; j++)
#pragma unroll
            for (int r = 0; r < 4; r++) c[i][j][r] = 0.f;

    cp16(sA0, Ar0); cp16(sA1, Ar1);
    cp16(sB0, Wr0); cp16(sB1, Wr1);
    asm volatile("cp.async.commit_group;\n" ::);

#pragma unroll 1
    for (int kt = 0; kt < NT; kt++) {
        const int s = kt & 1;
        if (kt + 1 < NT) {
            const int k = (kt + 1) * BK;
            const uint32_t so = (uint32_t)((kt + 1) & 1);
            cp16(sA0 + so * STAGE_A, Ar0 + k);
            cp16(sA1 + so * STAGE_A, Ar1 + k);
            cp16(sB0 + so * STAGE_B, Wr0 + k);
            cp16(sB1 + so * STAGE_B, Wr1 + k);
            asm volatile("cp.async.commit_group;\n" ::);
            asm volatile("cp.async.wait_group 1;\n" ::);
        } else {
            asm volatile("cp.async.wait_group 0;\n" ::);
        }
        __syncthreads();

#pragma unroll
        for (int kk = 0; kk < 2; kk++) {
            const int kb = kk * 8;
            uint32_t a[2][4];
#pragma unroll
            for (int i = 0; i < 2; i++) {
                const int m = wm + i * 16 + g;
                a[i][0] = As[s][m][kb + tg];
                a[i][1] = As[s][m + 8][kb + tg];
                a[i][2] = As[s][m][kb + tg + 4];
                a[i][3] = As[s][m + 8][kb + tg + 4];
            }
#pragma unroll
            for (int j = 0; j < 8; j++) {
                const int n = wn + j * 8 + g;
                const uint32_t b0 = Bs[s][n][kb + tg];
                const uint32_t b1 = Bs[s][n][kb + tg + 4];
                mma_tf32(c[0][j], a[0], b0, b1);
                mma_tf32(c[1][j], a[1], b0, b1);
            }
        }
        __syncthreads();
    }

#pragma unroll
    for (int i = 0; i < 2; i++) {
        const int mrow0 = m0 + wm + i * 16 + g;
#pragma unroll
        for (int j = 0; j < 8; j++) {
            const int ncol = n0 + wn + j * 8 + 2 * tg;
            *(float2*)&C[(size_t)mrow0 * ldc + ncol] =
                make_float2(c[i][j][0], c[i][j][1]);
            *(float2*)&C[(size_t)(mrow0 + 8) * ldc + ncol] =
                make_float2(c[i][j][2], c[i][j][3]);
        }
    }
}

// ---------------------------------------------------------------------------
extern "C" void kernel_launch(void* const* d_in, const int* in_sizes, int n_in,
                              void* d_out, int out_size)
{
    const float* x          = (const float*)d_in[0];
    const float* in_proj_w  = (const float*)d_in[1];
    const float* conv_w     = (const float*)d_in[2];
    const float* conv_b     = (const float*)d_in[3];
    const float* x_proj_w   = (const float*)d_in[4];
    const float* dt_proj_w  = (const float*)d_in[5];
    const float* dt_proj_b  = (const float*)d_in[6];
    const float* A_log      = (const float*)d_in[7];
    const float* D_param    = (const float*)d_in[8];
    const float* out_proj_w = (const float*)d_in[9];
    float* out = (float*)d_out;

    // 1) in_proj (tf32 mma) -> g_xz [4096,2048]
    gemm_mma1<<<dim3(2 * DINNER / 128, MROWS / 128), 256>>>(x, in_proj_w);

    // 2+3) conv+silu fused with x_proj -> g_xst, g_zt, g_xdbl (+ w6 cvt)
    conv_xproj<<<MROWS / 32, 256>>>(conv_w, conv_b, x_proj_w, out_proj_w);

    // 4) dt_proj + softplus -> g_deltat [2048 ch][2048 l]
    gemm_nt4<<<dim3(DINNER / 64, MROWS / 64), 256>>>(dt_proj_w, dt_proj_b);

    // 5a) chunk summaries
    scan_phaseA<<<dim3(NCHAN / 8, TCHUNK), 128>>>(A_log);
    // 5b) chunk-state composition
    scan_phaseB<<<NCHAN * DSTATE / 256, 256>>>();
    // 5c) per-chunk scan from h0 -> g_y
    scan_phaseC<<<dim3(NCHAN / 8, TCHUNK), 128>>>(A_log, D_param);

    // 6) out_proj (tf32 mma, cp.async) -> out [4096,512]
    gemm_mma6<<<dim3(DMODEL / 128, MROWS / 128), 256>>>(out);
}

// round 9
// speedup vs baseline: 2.8852x; 1.0224x over previous
#include <cuda_runtime.h>
#include <cuda_bf16.h>
#include <cstdint>

// ---------------------------------------------------------------------------
// Mamba block forward.  B=2, L=2048, d_model=512, d_inner=1024, d_state=16,
// dt_rank=32, d_conv=4.
// Launches: 1 cvt_pre      x, in_proj_w -> tf32 scratch
//           2 gemm_pipe<1> in_proj (tf32 mma, cp.async)
//           3 conv_xproj   conv+silu + x_proj fused; xs_t/z_t transposed
//           4 gemm_nt4     dt_proj + softplus -> delta_t (transposed)
//           5 scan_phaseA  per-chunk local scan summaries (h_end, decay)
//           6 scan_phaseB  chunk-state composition -> h0 per chunk
//           7 scan_phaseC  per-chunk full scan from h0 -> y
//           8 gemm_pipe<6> out_proj (tf32 mma, cp.async)
// ---------------------------------------------------------------------------

#define BATCH    2
#define SEQLEN   2048
#define DMODEL   512
#define DINNER   1024
#define DSTATE   16
#define DTRANK   32
#define DCONV    4
#define MROWS    (BATCH * SEQLEN)        // 4096
#define NCHAN    (BATCH * DINNER)        // 2048 scan channels
#define TCHUNK   16                      // scan chunks along L
#define CLEN     (SEQLEN / TCHUNK)       // 128 steps per chunk

// Scratch (device-global; no runtime allocation allowed)
__device__ float g_xz[(size_t)MROWS * 2 * DINNER];    // [4096, 2048]  xs | z
__device__ float g_xst[(size_t)NCHAN * SEQLEN];       // xs transposed [ch][l]
__device__ float g_zt[(size_t)NCHAN * SEQLEN];        // z transposed [ch][l]
__device__ float g_xdbl[(size_t)MROWS * 64];          // [4096, 64]
__device__ float g_deltat[(size_t)NCHAN * SEQLEN];    // delta transposed [ch][l]
__device__ float g_y[(size_t)MROWS * DINNER];         // scan output (tf32-rounded)
__device__ uint32_t g_w6tf[(size_t)DMODEL * DINNER];  // out_proj_w in tf32
__device__ uint32_t g_x1tf[(size_t)MROWS * DMODEL];   // x in tf32
__device__ uint32_t g_w1tf[(size_t)2 * DINNER * DMODEL]; // in_proj_w in tf32
__device__ float g_hend[(size_t)TCHUNK * NCHAN * DSTATE];
__device__ float g_decay[(size_t)TCHUNK * NCHAN * DSTATE];
__device__ float g_h0[(size_t)TCHUNK * NCHAN * DSTATE];

// ---------------------------------------------------------------------------
__device__ __forceinline__ uint32_t f2tf32(float f) {
    uint32_t r;
    asm("cvt.rna.tf32.f32 %0, %1;" : "=r"(r) : "f"(f));
    return r;
}

__device__ __forceinline__ void mma_tf32(float c[4], const uint32_t a[4],
                                         uint32_t b0, uint32_t b1) {
    asm volatile(
        "mma.sync.aligned.m16n8k8.row.col.f32.tf32.tf32.f32 "
        "{%0,%1,%2,%3}, {%4,%5,%6,%7}, {%8,%9}, {%0,%1,%2,%3};"
        : "+f"(c[0]), "+f"(c[1]), "+f"(c[2]), "+f"(c[3])
        : "r"(a[0]), "r"(a[1]), "r"(a[2]), "r"(a[3]), "r"(b0), "r"(b1));
}

__device__ __forceinline__ void cp16(uint32_t dst_smem, const void* src) {
    asm volatile("cp.async.cg.shared.global [%0], [%1], 16;\n"
                 :: "r"(dst_smem), "l"(src));
}

// ---------------------------------------------------------------------------
// Prepass: x and in_proj_w -> tf32.  3M floats, float4 per thread-iter.
// ---------------------------------------------------------------------------
__global__ void __launch_bounds__(256)
cvt_pre(const float* __restrict__ x, const float* __restrict__ in_proj_w)
{
    const size_t i4 = ((size_t)blockIdx.x * 256 + threadIdx.x) * 4;
    constexpr size_t NX = (size_t)MROWS * DMODEL;            // 2M
    constexpr size_t NW = (size_t)2 * DINNER * DMODEL;       // 1M
    if (i4 < NX) {
        float4 v = *(const float4*)&x[i4];
        uint4 p;
        p.x = f2tf32(v.x); p.y = f2tf32(v.y);
        p.z = f2tf32(v.z); p.w = f2tf32(v.w);
        *(uint4*)&g_x1tf[i4] = p;
    } else {
        const size_t j4 = i4 - NX;
        if (j4 < NW) {
            float4 v = *(const float4*)&in_proj_w[j4];
            uint4 p;
            p.x = f2tf32(v.x); p.y = f2tf32(v.y);
            p.z = f2tf32(v.z); p.w = f2tf32(v.w);
            *(uint4*)&g_w1tf[j4] = p;
        }
    }
}

// ---------------------------------------------------------------------------
// Pipelined tf32 NT GEMM (cp.async 2-stage), pre-converted tf32 inputs.
//   STAGE 1: A=g_x1tf, W=g_w1tf, C=g_xz, K=512,  ldc=2048
//   STAGE 6: A=g_y,    W=g_w6tf, C=out,  K=1024, ldc=512
// BM=BN=128, BK=16, 256 threads, warp tile 32x64.
// ---------------------------------------------------------------------------
template <int STAGE>
__global__ void __launch_bounds__(256)
gemm_pipe(float* __restrict__ Cp)
{
    constexpr int BM = 128, BN = 128, BK = 16, SST = BK + 4;
    constexpr int K   = (STAGE == 1) ? DMODEL : DINNER;
    constexpr int lda = K, ldw = K;
    constexpr int ldc = (STAGE == 1) ? 2 * DINNER : DMODEL;
    constexpr int NT  = K / BK;

    const uint32_t* Abase = (STAGE == 1) ? g_x1tf : (const uint32_t*)g_y;
    const uint32_t* Wbase = (STAGE == 1) ? g_w1tf : g_w6tf;
    float* C = (STAGE == 1) ? g_xz : Cp;

    __shared__ __align__(16) uint32_t As[2][BM][SST];
    __shared__ __align__(16) uint32_t Bs[2][BN][SST];

    const int tid = threadIdx.x;
    const int lane = tid & 31;
    const int wid = tid >> 5;
    const int wm = (wid & 3) * 32;
    const int wn = (wid >> 2) * 64;
    const int g  = lane >> 2;
    const int tg = lane & 3;

    const int m0 = blockIdx.y * BM;
    const int n0 = blockIdx.x * BN;

    const int lr0 = tid >> 2;
    const int lr1 = lr0 + 64;
    const int lc4 = (tid & 3) * 4;

    const uint32_t* Ar0 = Abase + (size_t)(m0 + lr0) * lda + lc4;
    const uint32_t* Ar1 = Abase + (size_t)(m0 + lr1) * lda + lc4;
    const uint32_t* Wr0 = Wbase + (size_t)(n0 + lr0) * ldw + lc4;
    const uint32_t* Wr1 = Wbase + (size_t)(n0 + lr1) * ldw + lc4;

    uint32_t sA0 = (uint32_t)__cvta_generic_to_shared(&As[0][lr0][lc4]);
    uint32_t sA1 = (uint32_t)__cvta_generic_to_shared(&As[0][lr1][lc4]);
    uint32_t sB0 = (uint32_t)__cvta_generic_to_shared(&Bs[0][lr0][lc4]);
    uint32_t sB1 = (uint32_t)__cvta_generic_to_shared(&Bs[0][lr1][lc4]);
    constexpr uint32_t STAGE_A = sizeof(uint32_t) * BM * SST;
    constexpr uint32_t STAGE_B = sizeof(uint32_t) * BN * SST;

    float c[2][8][4];
#pragma unroll
    for (int i = 0; i < 2; i++)
#pragma unroll
        for (int j = 0; j < 8; j++)
#pragma unroll
            for (int r = 0; r < 4; r++) c[i][j][r] = 0.f;

    cp16(sA0, Ar0); cp16(sA1, Ar1);
    cp16(sB0, Wr0); cp16(sB1, Wr1);
    asm volatile("cp.async.commit_group;\n" ::);

#pragma unroll 1
    for (int kt = 0; kt < NT; kt++) {
        const int s = kt & 1;
        if (kt + 1 < NT) {
            const int k = (kt + 1) * BK;
            const uint32_t so = (uint32_t)((kt + 1) & 1);
            cp16(sA0 + so * STAGE_A, Ar0 + k);
            cp16(sA1 + so * STAGE_A, Ar1 + k);
            cp16(sB0 + so * STAGE_B, Wr0 + k);
            cp16(sB1 + so * STAGE_B, Wr1 + k);
            asm volatile("cp.async.commit_group;\n" ::);
            asm volatile("cp.async.wait_group 1;\n" ::);
        } else {
            asm volatile("cp.async.wait_group 0;\n" ::);
        }
        __syncthreads();

#pragma unroll
        for (int kk = 0; kk < 2; kk++) {
            const int kb = kk * 8;
            uint32_t a[2][4];
#pragma unroll
            for (int i = 0; i < 2; i++) {
                const int m = wm + i * 16 + g;
                a[i][0] = As[s][m][kb + tg];
                a[i][1] = As[s][m + 8][kb + tg];
                a[i][2] = As[s][m][kb + tg + 4];
                a[i][3] = As[s][m + 8][kb + tg + 4];
            }
#pragma unroll
            for (int j = 0; j < 8; j++) {
                const int n = wn + j * 8 + g;
                const uint32_t b0 = Bs[s][n][kb + tg];
                const uint32_t b1 = Bs[s][n][kb + tg + 4];
                mma_tf32(c[0][j], a[0], b0, b1);
                mma_tf32(c[1][j], a[1], b0, b1);
            }
        }
        __syncthreads();
    }

#pragma unroll
    for (int i = 0; i < 2; i++) {
        const int mrow0 = m0 + wm + i * 16 + g;
#pragma unroll
        for (int j = 0; j < 8; j++) {
            const int ncol = n0 + wn + j * 8 + 2 * tg;
            *(float2*)&C[(size_t)mrow0 * ldc + ncol] =
                make_float2(c[i][j][0], c[i][j][1]);
            *(float2*)&C[(size_t)(mrow0 + 8) * ldc + ncol] =
                make_float2(c[i][j][2], c[i][j][3]);
        }
    }
}

// ---------------------------------------------------------------------------
// Stage 2+3 fused: conv1d+SiLU, x_proj GEMM; writes xs_t and z_t transposed.
// ---------------------------------------------------------------------------
__global__ void __launch_bounds__(256)
conv_xproj(const float* __restrict__ conv_w,
           const float* __restrict__ conv_b,
           const float* __restrict__ x_proj_w,
           const float* __restrict__ out_proj_w)
{
    __shared__ float sxs[32][68];
    __shared__ float sw[64][68];
    __shared__ float sz[32][68];

    const int tid = threadIdx.x;
    const int bl0 = blockIdx.x * 32;
    const int b   = bl0 >> 11;
    const int l0  = bl0 & 2047;
    const int tx = tid & 15;
    const int ty = tid >> 4;

    float acc[2][4];
#pragma unroll
    for (int i = 0; i < 2; i++)
#pragma unroll
        for (int j = 0; j < 4; j++) acc[i][j] = 0.f;

#pragma unroll 1
    for (int d0 = 0; d0 < DINNER; d0 += 64) {
        __syncthreads();
#pragma unroll
        for (int it = 0; it < 4; it++) {
            const int idx = tid + it * 256;
            const int e = idx >> 4, c4 = (idx & 15) * 4;
            *(float4*)&sw[e][c4] =
                *(const float4*)&x_proj_w[(size_t)e * DINNER + d0 + c4];
        }
#pragma unroll
        for (int it = 0; it < 8; it++) {
            const int idx = tid + it * 256;
            const int r = idx >> 6, dc = idx & 63;
            const int bl = bl0 + r;
            const int l = bl & (SEQLEN - 1);
            const int d = d0 + dc;
            float a = conv_b[d];
#pragma unroll
            for (int j = 0; j < DCONV; j++) {
                const int ls = l - (DCONV - 1) + j;
                if (ls >= 0)
                    a = fmaf(g_xz[(size_t)(bl - (DCONV - 1) + j) * (2 * DINNER) + d],
                             conv_w[d * DCONV + j], a);
            }
            sxs[r][dc] = a / (1.f + __expf(-a));     // SiLU
            sz[r][dc] = g_xz[(size_t)bl * (2 * DINNER) + DINNER + d];
        }
        __syncthreads();
        {
            const int dloc = tid >> 2;
            const int lq = (tid & 3) * 8;
            const size_t row = (size_t)(b * DINNER + d0 + dloc) * SEQLEN + l0 + lq;
            float4 v0, v1;
            v0.x = sxs[lq + 0][dloc]; v0.y = sxs[lq + 1][dloc];
            v0.z = sxs[lq + 2][dloc]; v0.w = sxs[lq + 3][dloc];
            v1.x = sxs[lq + 4][dloc]; v1.y = sxs[lq + 5][dloc];
            v1.z = sxs[lq + 6][dloc]; v1.w = sxs[lq + 7][dloc];
            *(float4*)&g_xst[row] = v0;
            *(float4*)&g_xst[row + 4] = v1;
            v0.x = sz[lq + 0][dloc]; v0.y = sz[lq + 1][dloc];
            v0.z = sz[lq + 2][dloc]; v0.w = sz[lq + 3][dloc];
            v1.x = sz[lq + 4][dloc]; v1.y = sz[lq + 5][dloc];
            v1.z = sz[lq + 6][dloc]; v1.w = sz[lq + 7][dloc];
            *(float4*)&g_zt[row] = v0;
            *(float4*)&g_zt[row + 4] = v1;
        }
#pragma unroll
        for (int kk = 0; kk < 64; kk++) {
            float ar[2], br[4];
#pragma unroll
            for (int i = 0; i < 2; i++) ar[i] = sxs[ty * 2 + i][kk];
#pragma unroll
            for (int j = 0; j < 4; j++) br[j] = sw[tx * 4 + j][kk];
#pragma unroll
            for (int i = 0; i < 2; i++)
#pragma unroll
                for (int j = 0; j < 4; j++)
                    acc[i][j] = fmaf(ar[i], br[j], acc[i][j]);
        }
    }

#pragma unroll
    for (int i = 0; i < 2; i++)
#pragma unroll
        for (int j = 0; j < 4; j++)
            g_xdbl[(size_t)(bl0 + ty * 2 + i) * 64 + tx * 4 + j] = acc[i][j];

    const size_t base = (size_t)blockIdx.x * 4096;
#pragma unroll
    for (int it = 0; it < 4; it++) {
        const size_t off = base + (size_t)it * 1024 + tid * 4;
        float4 w4 = *(const float4*)&out_proj_w[off];
        uint4 p;
        p.x = f2tf32(w4.x); p.y = f2tf32(w4.y);
        p.z = f2tf32(w4.z); p.w = f2tf32(w4.w);
        *(uint4*)&g_w6tf[off] = p;
    }
}

// ---------------------------------------------------------------------------
// Stage 4: dt_proj + softplus -> delta_t[ch][l] (transposed write).
// ---------------------------------------------------------------------------
__global__ void __launch_bounds__(256)
gemm_nt4(const float* __restrict__ W, const float* __restrict__ bias)
{
    constexpr int BM = 64, BN = 64, BK = 16;
    constexpr int lda = 64, ldw = DTRANK, K = DTRANK;
    const float* A = g_xdbl;

    __shared__ float As[BK][BM];
    __shared__ float Bs[BK][BN];

    const int tid = threadIdx.x;
    const int m0 = blockIdx.y * BM;
    const int n0 = blockIdx.x * BN;
    const int tx = tid & 15;
    const int ty = tid >> 4;
    const int lrow = tid >> 2;
    const int lc4 = (tid & 3) * 4;

    float acc[4][4];
#pragma unroll
    for (int i = 0; i < 4; i++)
#pragma unroll
        for (int j = 0; j < 4; j++) acc[i][j] = 0.f;

    const float* Arow = A + (size_t)(m0 + lrow) * lda + lc4;
    const float* Wrow = W + (size_t)(n0 + lrow) * ldw + lc4;

#pragma unroll 1
    for (int k0 = 0; k0 < K; k0 += BK) {
        float4 av = *(const float4*)(Arow + k0);
        float4 wv = *(const float4*)(Wrow + k0);
        __syncthreads();
        As[lc4 + 0][lrow] = av.x; As[lc4 + 1][lrow] = av.y;
        As[lc4 + 2][lrow] = av.z; As[lc4 + 3][lrow] = av.w;
        Bs[lc4 + 0][lrow] = wv.x; Bs[lc4 + 1][lrow] = wv.y;
        Bs[lc4 + 2][lrow] = wv.z; Bs[lc4 + 3][lrow] = wv.w;
        __syncthreads();
#pragma unroll
        for (int kk = 0; kk < BK; kk++) {
            float4 a4 = *(const float4*)&As[kk][ty * 4];
            float4 b4 = *(const float4*)&Bs[kk][tx * 4];
            float ar[4] = {a4.x, a4.y, a4.z, a4.w};
            float br[4] = {b4.x, b4.y, b4.z, b4.w};
#pragma unroll
            for (int i = 0; i < 4; i++)
#pragma unroll
                for (int j = 0; j < 4; j++)
                    acc[i][j] = fmaf(ar[i], br[j], acc[i][j]);
        }
    }

    const int b = m0 >> 11;
    const int lb = (m0 & 2047) + ty * 4;
#pragma unroll
    for (int j = 0; j < 4; j++) {
        const int n = n0 + tx * 4 + j;
        float sp[4];
#pragma unroll
        for (int i = 0; i < 4; i++) {
            float v = acc[i][j] + bias[n];
            sp[i] = (v > 20.f) ? v : log1pf(__expf(v));
        }
        *(float4*)&g_deltat[(size_t)(b * DINNER + n) * SEQLEN + lb] =
            make_float4(sp[0], sp[1], sp[2], sp[3]);
    }
}

// ---------------------------------------------------------------------------
// Scan phase A: per-chunk local scan -> h_end, decay.  dt/u loaded as
// float4 broadcast (4 steps per LDG.128), B per-step (coalesced over n).
// ---------------------------------------------------------------------------
__global__ void __launch_bounds__(128)
scan_phaseA(const float* __restrict__ A_log)
{
    const int tid = threadIdx.x;
    const int ch = tid >> 4;
    const int n  = tid & 15;
    const int chg = blockIdx.x * 8 + ch;
    const int t = blockIdx.y;
    const int b = chg >> 10;
    const int d = chg & (DINNER - 1);

    const float A_dn = -__expf(A_log[d * DSTATE + n]);
    const float* dl = g_deltat + (size_t)chg * SEQLEN + t * CLEN;
    const float* us = g_xst    + (size_t)chg * SEQLEN + t * CLEN;
    const float* xd = g_xdbl + ((size_t)b * SEQLEN + t * CLEN) * 64 + 32 + n;

    float h = 0.f, pref = 1.f;
#pragma unroll 1
    for (int l4 = 0; l4 < CLEN; l4 += 4) {
        const float4 d4 = *(const float4*)(dl + l4);
        const float4 u4 = *(const float4*)(us + l4);
        const float dts[4] = {d4.x, d4.y, d4.z, d4.w};
        const float uus[4] = {u4.x, u4.y, u4.z, u4.w};
#pragma unroll
        for (int j = 0; j < 4; j++) {
            const float Bn = xd[(size_t)(l4 + j) * 64];
            const float dA = __expf(dts[j] * A_dn);
            h = fmaf(dA, h, dts[j] * uus[j] * Bn);
            pref *= dA;
        }
    }
    const size_t o = ((size_t)t * NCHAN + chg) * DSTATE + n;
    g_hend[o] = h;
    g_decay[o] = pref;
}

// ---------------------------------------------------------------------------
// Scan phase B: compose chunk states serially over T chunks.
// ---------------------------------------------------------------------------
__global__ void __launch_bounds__(256)
scan_phaseB()
{
    const int id = blockIdx.x * 256 + threadIdx.x;   // 0..NCHAN*DSTATE-1
    float h = 0.f;
#pragma unroll
    for (int t = 0; t < TCHUNK; t++) {
        const size_t o = (size_t)t * NCHAN * DSTATE + id;
        g_h0[o] = h;
        h = g_decay[o] * h + g_hend[o];
    }
}

// ---------------------------------------------------------------------------
// Scan phase C: full scan per chunk starting from h0; cp.async pipelined.
// ---------------------------------------------------------------------------
__global__ void __launch_bounds__(128)
scan_phaseC(const float* __restrict__ A_log,
            const float* __restrict__ D_param)
{
    constexpr int CH = 32, NCHK = CLEN / CH, SP = CH + 4;
    __shared__ __align__(16) float s_dt[2][8][SP];
    __shared__ __align__(16) float s_u [2][8][SP];
    __shared__ __align__(16) float s_z [2][8][SP];
    __shared__ __align__(16) float s_bc[2][CH][32];
    __shared__ float s_y[CH][8];

    const int tid = threadIdx.x;
    const int ch  = tid >> 4;
    const int n   = tid & 15;
    const int c0  = blockIdx.x * 8;
    const int t   = blockIdx.y;
    const int b   = c0 >> 10;
    const int d   = (c0 + ch) & (DINNER - 1);
    const int lbase = t * CLEN;

    const float A_dn = -__expf(A_log[d * DSTATE + n]);
    const float Dd = D_param[d];
    const float* xd = g_xdbl + (size_t)b * SEQLEN * 64;

    auto fill = [&](int s, int c) {
        const int l0 = lbase + c * CH;
#pragma unroll
        for (int it = 0; it < 2; it++) {
            const int id = tid + it * 128;
            if (id < 192) {
                const int st = id >> 6;
                const int r = id & 63;
                const int cc = r >> 3, q = (r & 7) * 4;
                const size_t src = (size_t)(c0 + cc) * SEQLEN + l0 + q;
                if (st == 0)
                    cp16((uint32_t)__cvta_generic_to_shared(&s_dt[s][cc][q]),
                         g_deltat + src);
                else if (st == 1)
                    cp16((uint32_t)__cvta_generic_to_shared(&s_u[s][cc][q]),
                         g_xst + src);
                else
                    cp16((uint32_t)__cvta_generic_to_shared(&s_z[s][cc][q]),
                         g_zt + src);
            }
        }
#pragma unroll
        for (int it = 0; it < 2; it++) {
            const int id = tid + it * 128;
            const int j = id >> 3, q = (id & 7) * 4;
            cp16((uint32_t)__cvta_generic_to_shared(&s_bc[s][j][q]),
                 xd + (size_t)(l0 + j) * 64 + 32 + q);
        }
    };

    fill(0, 0); asm volatile("cp.async.commit_group;\n" ::);
    fill(1, 1); asm volatile("cp.async.commit_group;\n" ::);

    float h = g_h0[(size_t)t * NCHAN * DSTATE + (size_t)(c0 + ch) * DSTATE + n];
#pragma unroll 1
    for (int c = 0; c < NCHK; c++) {
        const int s = c & 1;
        if (c < NCHK - 1) asm volatile("cp.async.wait_group 1;\n" ::);
        else              asm volatile("cp.async.wait_group 0;\n" ::);
        __syncthreads();
#pragma unroll
        for (int j = 0; j < CH; j++) {
            const float dt_c = s_dt[s][ch][j];
            const float u_c  = s_u[s][ch][j];
            const float dA = __expf(dt_c * A_dn);
            const float Bn = s_bc[s][j][n];
            const float Cn = s_bc[s][j][16 + n];
            h = fmaf(dA, h, dt_c * u_c * Bn);
            float p = h * Cn;
            p += __shfl_xor_sync(0xffffffffu, p, 8, 16);
            p += __shfl_xor_sync(0xffffffffu, p, 4, 16);
            p += __shfl_xor_sync(0xffffffffu, p, 2, 16);
            p += __shfl_xor_sync(0xffffffffu, p, 1, 16);
            if (n == 0) {
                const float z = s_z[s][ch][j];
                const float sz = z / (1.f + __expf(-z));
                s_y[j][ch] = __uint_as_float(f2tf32((p + u_c * Dd) * sz));
            }
        }
        __syncthreads();
        const int l0 = lbase + c * CH;
#pragma unroll
        for (int it = 0; it < 2; it++) {
            const int id = tid + it * 128;
            const int j = id >> 3, cc = id & 7;
            g_y[(size_t)(b * SEQLEN + l0 + j) * DINNER + (c0 & (DINNER - 1)) + cc] =
                s_y[j][cc];
        }
        if (c + 2 < NCHK) { fill(s, c + 2); asm volatile("cp.async.commit_group;\n" ::); }
    }
}

// ---------------------------------------------------------------------------
extern "C" void kernel_launch(void* const* d_in, const int* in_sizes, int n_in,
                              void* d_out, int out_size)
{
    const float* x          = (const float*)d_in[0];
    const float* in_proj_w  = (const float*)d_in[1];
    const float* conv_w     = (const float*)d_in[2];
    const float* conv_b     = (const float*)d_in[3];
    const float* x_proj_w   = (const float*)d_in[4];
    const float* dt_proj_w  = (const float*)d_in[5];
    const float* dt_proj_b  = (const float*)d_in[6];
    const float* A_log      = (const float*)d_in[7];
    const float* D_param    = (const float*)d_in[8];
    const float* out_proj_w = (const float*)d_in[9];
    float* out = (float*)d_out;

    // 0) x, in_proj_w -> tf32 scratch (3M floats / 4 per thread)
    cvt_pre<<<3 * 1024 * 1024 / 4 / 256, 256>>>(x, in_proj_w);

    // 1) in_proj (tf32 mma, cp.async) -> g_xz [4096,2048]
    gemm_pipe<1><<<dim3(2 * DINNER / 128, MROWS / 128), 256>>>(nullptr);

    // 2+3) conv+silu fused with x_proj -> g_xst, g_zt, g_xdbl (+ w6 cvt)
    conv_xproj<<<MROWS / 32, 256>>>(conv_w, conv_b, x_proj_w, out_proj_w);

    // 4) dt_proj + softplus -> g_deltat [2048 ch][2048 l]
    gemm_nt4<<<dim3(DINNER / 64, MROWS / 64), 256>>>(dt_proj_w, dt_proj_b);

    // 5a) chunk summaries
    scan_phaseA<<<dim3(NCHAN / 8, TCHUNK), 128>>>(A_log);
    // 5b) chunk-state composition
    scan_phaseB<<<NCHAN * DSTATE / 256, 256>>>();
    // 5c) per-chunk scan from h0 -> g_y
    scan_phaseC<<<dim3(NCHAN / 8, TCHUNK), 128>>>(A_log, D_param);

    // 6) out_proj (tf32 mma, cp.async) -> out [4096,512]
    gemm_pipe<6><<<dim3(DMODEL / 128, MROWS / 128), 256>>>(out);
}

// round 10
// speedup vs baseline: 3.4158x; 1.1839x over previous
#include <cuda_runtime.h>
#include <cuda_bf16.h>
#include <cstdint>

// ---------------------------------------------------------------------------
// Mamba block forward.  B=2, L=2048, d_model=512, d_inner=1024, d_state=16,
// dt_rank=32, d_conv=4.
// Launches: 1 cvt_pre      x, in_proj_w -> tf32 scratch
//           2 gemm_pipe<1> in_proj (tf32 mma, cp.async)
//           3 conv_xproj   conv+silu + x_proj fused; xs_t/z_t transposed
//           4 gemm_nt4     dt_proj + softplus -> delta_t (transposed)
//           5 scan_phaseA  thread-per-channel chunk summaries (h in regs)
//           6 scan_phaseB  chunk-state composition -> h0 per chunk
//           7 scan_phaseC  thread-per-channel scan from h0 -> y (no shfl)
//           8 gemm_pipe<6> out_proj (tf32 mma, cp.async)
// ---------------------------------------------------------------------------

#define BATCH    2
#define SEQLEN   2048
#define DMODEL   512
#define DINNER   1024
#define DSTATE   16
#define DTRANK   32
#define DCONV    4
#define MROWS    (BATCH * SEQLEN)        // 4096
#define NCHAN    (BATCH * DINNER)        // 2048 scan channels
#define TCHUNK   32                      // scan chunks along L
#define CLEN     (SEQLEN / TCHUNK)       // 64 steps per chunk

// Scratch (device-global; no runtime allocation allowed)
__device__ float g_xz[(size_t)MROWS * 2 * DINNER];    // [4096, 2048]  xs | z
__device__ float g_xst[(size_t)NCHAN * SEQLEN];       // xs transposed [ch][l]
__device__ float g_zt[(size_t)NCHAN * SEQLEN];        // z transposed [ch][l]
__device__ float g_xdbl[(size_t)MROWS * 64];          // [4096, 64]
__device__ float g_deltat[(size_t)NCHAN * SEQLEN];    // delta transposed [ch][l]
__device__ float g_y[(size_t)MROWS * DINNER];         // scan output (tf32-rounded)
__device__ uint32_t g_w6tf[(size_t)DMODEL * DINNER];  // out_proj_w in tf32
__device__ uint32_t g_x1tf[(size_t)MROWS * DMODEL];   // x in tf32
__device__ uint32_t g_w1tf[(size_t)2 * DINNER * DMODEL]; // in_proj_w in tf32
__device__ float g_hend[(size_t)TCHUNK * NCHAN * DSTATE];
__device__ float g_decay[(size_t)TCHUNK * NCHAN * DSTATE];
__device__ float g_h0[(size_t)TCHUNK * NCHAN * DSTATE];

// ---------------------------------------------------------------------------
__device__ __forceinline__ uint32_t f2tf32(float f) {
    uint32_t r;
    asm("cvt.rna.tf32.f32 %0, %1;" : "=r"(r) : "f"(f));
    return r;
}

__device__ __forceinline__ void mma_tf32(float c[4], const uint32_t a[4],
                                         uint32_t b0, uint32_t b1) {
    asm volatile(
        "mma.sync.aligned.m16n8k8.row.col.f32.tf32.tf32.f32 "
        "{%0,%1,%2,%3}, {%4,%5,%6,%7}, {%8,%9}, {%0,%1,%2,%3};"
        : "+f"(c[0]), "+f"(c[1]), "+f"(c[2]), "+f"(c[3])
        : "r"(a[0]), "r"(a[1]), "r"(a[2]), "r"(a[3]), "r"(b0), "r"(b1));
}

__device__ __forceinline__ void cp16(uint32_t dst_smem, const void* src) {
    asm volatile("cp.async.cg.shared.global [%0], [%1], 16;\n"
                 :: "r"(dst_smem), "l"(src));
}

// ---------------------------------------------------------------------------
// Prepass: x and in_proj_w -> tf32.  3M floats, float4 per thread-iter.
// ---------------------------------------------------------------------------
__global__ void __launch_bounds__(256)
cvt_pre(const float* __restrict__ x, const float* __restrict__ in_proj_w)
{
    const size_t i4 = ((size_t)blockIdx.x * 256 + threadIdx.x) * 4;
    constexpr size_t NX = (size_t)MROWS * DMODEL;            // 2M
    constexpr size_t NW = (size_t)2 * DINNER * DMODEL;       // 1M
    if (i4 < NX) {
        float4 v = *(const float4*)&x[i4];
        uint4 p;
        p.x = f2tf32(v.x); p.y = f2tf32(v.y);
        p.z = f2tf32(v.z); p.w = f2tf32(v.w);
        *(uint4*)&g_x1tf[i4] = p;
    } else {
        const size_t j4 = i4 - NX;
        if (j4 < NW) {
            float4 v = *(const float4*)&in_proj_w[j4];
            uint4 p;
            p.x = f2tf32(v.x); p.y = f2tf32(v.y);
            p.z = f2tf32(v.z); p.w = f2tf32(v.w);
            *(uint4*)&g_w1tf[j4] = p;
        }
    }
}

// ---------------------------------------------------------------------------
// Pipelined tf32 NT GEMM (cp.async 2-stage), pre-converted tf32 inputs.
//   STAGE 1: A=g_x1tf, W=g_w1tf, C=g_xz, K=512,  ldc=2048
//   STAGE 6: A=g_y,    W=g_w6tf, C=out,  K=1024, ldc=512
// ---------------------------------------------------------------------------
template <int STAGE>
__global__ void __launch_bounds__(256)
gemm_pipe(float* __restrict__ Cp)
{
    constexpr int BM = 128, BN = 128, BK = 16, SST = BK + 4;
    constexpr int K   = (STAGE == 1) ? DMODEL : DINNER;
    constexpr int lda = K, ldw = K;
    constexpr int ldc = (STAGE == 1) ? 2 * DINNER : DMODEL;
    constexpr int NT  = K / BK;

    const uint32_t* Abase = (STAGE == 1) ? g_x1tf : (const uint32_t*)g_y;
    const uint32_t* Wbase = (STAGE == 1) ? g_w1tf : g_w6tf;
    float* C = (STAGE == 1) ? g_xz : Cp;

    __shared__ __align__(16) uint32_t As[2][BM][SST];
    __shared__ __align__(16) uint32_t Bs[2][BN][SST];

    const int tid = threadIdx.x;
    const int lane = tid & 31;
    const int wid = tid >> 5;
    const int wm = (wid & 3) * 32;
    const int wn = (wid >> 2) * 64;
    const int g  = lane >> 2;
    const int tg = lane & 3;

    const int m0 = blockIdx.y * BM;
    const int n0 = blockIdx.x * BN;

    const int lr0 = tid >> 2;
    const int lr1 = lr0 + 64;
    const int lc4 = (tid & 3) * 4;

    const uint32_t* Ar0 = Abase + (size_t)(m0 + lr0) * lda + lc4;
    const uint32_t* Ar1 = Abase + (size_t)(m0 + lr1) * lda + lc4;
    const uint32_t* Wr0 = Wbase + (size_t)(n0 + lr0) * ldw + lc4;
    const uint32_t* Wr1 = Wbase + (size_t)(n0 + lr1) * ldw + lc4;

    uint32_t sA0 = (uint32_t)__cvta_generic_to_shared(&As[0][lr0][lc4]);
    uint32_t sA1 = (uint32_t)__cvta_generic_to_shared(&As[0][lr1][lc4]);
    uint32_t sB0 = (uint32_t)__cvta_generic_to_shared(&Bs[0][lr0][lc4]);
    uint32_t sB1 = (uint32_t)__cvta_generic_to_shared(&Bs[0][lr1][lc4]);
    constexpr uint32_t STAGE_A = sizeof(uint32_t) * BM * SST;
    constexpr uint32_t STAGE_B = sizeof(uint32_t) * BN * SST;

    float c[2][8][4];
#pragma unroll
    for (int i = 0; i < 2; i++)
#pragma unroll
        for (int j = 0; j < 8; j++)
#pragma unroll
            for (int r = 0; r < 4; r++) c[i][j][r] = 0.f;

    cp16(sA0, Ar0); cp16(sA1, Ar1);
    cp16(sB0, Wr0); cp16(sB1, Wr1);
    asm volatile("cp.async.commit_group;\n" ::);

#pragma unroll 1
    for (int kt = 0; kt < NT; kt++) {
        const int s = kt & 1;
        if (kt + 1 < NT) {
            const int k = (kt + 1) * BK;
            const uint32_t so = (uint32_t)((kt + 1) & 1);
            cp16(sA0 + so * STAGE_A, Ar0 + k);
            cp16(sA1 + so * STAGE_A, Ar1 + k);
            cp16(sB0 + so * STAGE_B, Wr0 + k);
            cp16(sB1 + so * STAGE_B, Wr1 + k);
            asm volatile("cp.async.commit_group;\n" ::);
            asm volatile("cp.async.wait_group 1;\n" ::);
        } else {
            asm volatile("cp.async.wait_group 0;\n" ::);
        }
        __syncthreads();

#pragma unroll
        for (int kk = 0; kk < 2; kk++) {
            const int kb = kk * 8;
            uint32_t a[2][4];
#pragma unroll
            for (int i = 0; i < 2; i++) {
                const int m = wm + i * 16 + g;
                a[i][0] = As[s][m][kb + tg];
                a[i][1] = As[s][m + 8][kb + tg];
                a[i][2] = As[s][m][kb + tg + 4];
                a[i][3] = As[s][m + 8][kb + tg + 4];
            }
#pragma unroll
            for (int j = 0; j < 8; j++) {
                const int n = wn + j * 8 + g;
                const uint32_t b0 = Bs[s][n][kb + tg];
                const uint32_t b1 = Bs[s][n][kb + tg + 4];
                mma_tf32(c[0][j], a[0], b0, b1);
                mma_tf32(c[1][j], a[1], b0, b1);
            }
        }
        __syncthreads();
    }

#pragma unroll
    for (int i = 0; i < 2; i++) {
        const int mrow0 = m0 + wm + i * 16 + g;
#pragma unroll
        for (int j = 0; j < 8; j++) {
            const int ncol = n0 + wn + j * 8 + 2 * tg;
            *(float2*)&C[(size_t)mrow0 * ldc + ncol] =
                make_float2(c[i][j][0], c[i][j][1]);
            *(float2*)&C[(size_t)(mrow0 + 8) * ldc + ncol] =
                make_float2(c[i][j][2], c[i][j][3]);
        }
    }
}

// ---------------------------------------------------------------------------
// Stage 2+3 fused: conv1d+SiLU, x_proj GEMM; writes xs_t and z_t transposed.
// ---------------------------------------------------------------------------
__global__ void __launch_bounds__(256)
conv_xproj(const float* __restrict__ conv_w,
           const float* __restrict__ conv_b,
           const float* __restrict__ x_proj_w,
           const float* __restrict__ out_proj_w)
{
    __shared__ float sxs[32][68];
    __shared__ float sw[64][68];
    __shared__ float sz[32][68];

    const int tid = threadIdx.x;
    const int bl0 = blockIdx.x * 32;
    const int b   = bl0 >> 11;
    const int l0  = bl0 & 2047;
    const int tx = tid & 15;
    const int ty = tid >> 4;

    float acc[2][4];
#pragma unroll
    for (int i = 0; i < 2; i++)
#pragma unroll
        for (int j = 0; j < 4; j++) acc[i][j] = 0.f;

#pragma unroll 1
    for (int d0 = 0; d0 < DINNER; d0 += 64) {
        __syncthreads();
#pragma unroll
        for (int it = 0; it < 4; it++) {
            const int idx = tid + it * 256;
            const int e = idx >> 4, c4 = (idx & 15) * 4;
            *(float4*)&sw[e][c4] =
                *(const float4*)&x_proj_w[(size_t)e * DINNER + d0 + c4];
        }
#pragma unroll
        for (int it = 0; it < 8; it++) {
            const int idx = tid + it * 256;
            const int r = idx >> 6, dc = idx & 63;
            const int bl = bl0 + r;
            const int l = bl & (SEQLEN - 1);
            const int d = d0 + dc;
            float a = conv_b[d];
#pragma unroll
            for (int j = 0; j < DCONV; j++) {
                const int ls = l - (DCONV - 1) + j;
                if (ls >= 0)
                    a = fmaf(g_xz[(size_t)(bl - (DCONV - 1) + j) * (2 * DINNER) + d],
                             conv_w[d * DCONV + j], a);
            }
            sxs[r][dc] = a / (1.f + __expf(-a));     // SiLU
            sz[r][dc] = g_xz[(size_t)bl * (2 * DINNER) + DINNER + d];
        }
        __syncthreads();
        {
            const int dloc = tid >> 2;
            const int lq = (tid & 3) * 8;
            const size_t row = (size_t)(b * DINNER + d0 + dloc) * SEQLEN + l0 + lq;
            float4 v0, v1;
            v0.x = sxs[lq + 0][dloc]; v0.y = sxs[lq + 1][dloc];
            v0.z = sxs[lq + 2][dloc]; v0.w = sxs[lq + 3][dloc];
            v1.x = sxs[lq + 4][dloc]; v1.y = sxs[lq + 5][dloc];
            v1.z = sxs[lq + 6][dloc]; v1.w = sxs[lq + 7][dloc];
            *(float4*)&g_xst[row] = v0;
            *(float4*)&g_xst[row + 4] = v1;
            v0.x = sz[lq + 0][dloc]; v0.y = sz[lq + 1][dloc];
            v0.z = sz[lq + 2][dloc]; v0.w = sz[lq + 3][dloc];
            v1.x = sz[lq + 4][dloc]; v1.y = sz[lq + 5][dloc];
            v1.z = sz[lq + 6][dloc]; v1.w = sz[lq + 7][dloc];
            *(float4*)&g_zt[row] = v0;
            *(float4*)&g_zt[row + 4] = v1;
        }
#pragma unroll
        for (int kk = 0; kk < 64; kk++) {
            float ar[2], br[4];
#pragma unroll
            for (int i = 0; i < 2; i++) ar[i] = sxs[ty * 2 + i][kk];
#pragma unroll
            for (int j = 0; j < 4; j++) br[j] = sw[tx * 4 + j][kk];
#pragma unroll
            for (int i = 0; i < 2; i++)
#pragma unroll
                for (int j = 0; j < 4; j++)
                    acc[i][j] = fmaf(ar[i], br[j], acc[i][j]);
        }
    }

#pragma unroll
    for (int i = 0; i < 2; i++)
#pragma unroll
        for (int j = 0; j < 4; j++)
            g_xdbl[(size_t)(bl0 + ty * 2 + i) * 64 + tx * 4 + j] = acc[i][j];

    const size_t base = (size_t)blockIdx.x * 4096;
#pragma unroll
    for (int it = 0; it < 4; it++) {
        const size_t off = base + (size_t)it * 1024 + tid * 4;
        float4 w4 = *(const float4*)&out_proj_w[off];
        uint4 p;
        p.x = f2tf32(w4.x); p.y = f2tf32(w4.y);
        p.z = f2tf32(w4.z); p.w = f2tf32(w4.w);
        *(uint4*)&g_w6tf[off] = p;
    }
}

// ---------------------------------------------------------------------------
// Stage 4: dt_proj + softplus -> delta_t[ch][l] (transposed write).
// ---------------------------------------------------------------------------
__global__ void __launch_bounds__(256)
gemm_nt4(const float* __restrict__ W, const float* __restrict__ bias)
{
    constexpr int BM = 64, BN = 64, BK = 16;
    constexpr int lda = 64, ldw = DTRANK, K = DTRANK;
    const float* A = g_xdbl;

    __shared__ float As[BK][BM];
    __shared__ float Bs[BK][BN];

    const int tid = threadIdx.x;
    const int m0 = blockIdx.y * BM;
    const int n0 = blockIdx.x * BN;
    const int tx = tid & 15;
    const int ty = tid >> 4;
    const int lrow = tid >> 2;
    const int lc4 = (tid & 3) * 4;

    float acc[4][4];
#pragma unroll
    for (int i = 0; i < 4; i++)
#pragma unroll
        for (int j = 0; j < 4; j++) acc[i][j] = 0.f;

    const float* Arow = A + (size_t)(m0 + lrow) * lda + lc4;
    const float* Wrow = W + (size_t)(n0 + lrow) * ldw + lc4;

#pragma unroll 1
    for (int k0 = 0; k0 < K; k0 += BK) {
        float4 av = *(const float4*)(Arow + k0);
        float4 wv = *(const float4*)(Wrow + k0);
        __syncthreads();
        As[lc4 + 0][lrow] = av.x; As[lc4 + 1][lrow] = av.y;
        As[lc4 + 2][lrow] = av.z; As[lc4 + 3][lrow] = av.w;
        Bs[lc4 + 0][lrow] = wv.x; Bs[lc4 + 1][lrow] = wv.y;
        Bs[lc4 + 2][lrow] = wv.z; Bs[lc4 + 3][lrow] = wv.w;
        __syncthreads();
#pragma unroll
        for (int kk = 0; kk < BK; kk++) {
            float4 a4 = *(const float4*)&As[kk][ty * 4];
            float4 b4 = *(const float4*)&Bs[kk][tx * 4];
            float ar[4] = {a4.x, a4.y, a4.z, a4.w};
            float br[4] = {b4.x, b4.y, b4.z, b4.w};
#pragma unroll
            for (int i = 0; i < 4; i++)
#pragma unroll
                for (int j = 0; j < 4; j++)
                    acc[i][j] = fmaf(ar[i], br[j], acc[i][j]);
        }
    }

    const int b = m0 >> 11;
    const int lb = (m0 & 2047) + ty * 4;
#pragma unroll
    for (int j = 0; j < 4; j++) {
        const int n = n0 + tx * 4 + j;
        float sp[4];
#pragma unroll
        for (int i = 0; i < 4; i++) {
            float v = acc[i][j] + bias[n];
            sp[i] = (v > 20.f) ? v : log1pf(__expf(v));
        }
        *(float4*)&g_deltat[(size_t)(b * DINNER + n) * SEQLEN + lb] =
            make_float4(sp[0], sp[1], sp[2], sp[3]);
    }
}

// ---------------------------------------------------------------------------
// Scan phase A: thread-per-channel; all 16 states in registers.
// Grid (NCHAN/128, TCHUNK), 128 threads.  decay = exp(A_dn * sum(dt)).
// ---------------------------------------------------------------------------
__global__ void __launch_bounds__(128)
scan_phaseA(const float* __restrict__ A_log)
{
    const int tid = threadIdx.x;
    const int ch = blockIdx.x * 128 + tid;     // global channel
    const int t  = blockIdx.y;
    const int b  = ch >> 10;
    const int d  = ch & (DINNER - 1);

    float A_dn[DSTATE];
#pragma unroll
    for (int q = 0; q < 4; q++) {
        float4 a4 = *(const float4*)&A_log[d * DSTATE + q * 4];
        A_dn[q * 4 + 0] = -__expf(a4.x);
        A_dn[q * 4 + 1] = -__expf(a4.y);
        A_dn[q * 4 + 2] = -__expf(a4.z);
        A_dn[q * 4 + 3] = -__expf(a4.w);
    }

    const float* dl = g_deltat + (size_t)ch * SEQLEN + t * CLEN;
    const float* us = g_xst    + (size_t)ch * SEQLEN + t * CLEN;
    const float* xb = g_xdbl + ((size_t)b * SEQLEN + t * CLEN) * 64 + 32;

    float h[DSTATE];
#pragma unroll
    for (int n = 0; n < DSTATE; n++) h[n] = 0.f;
    float sdt = 0.f;

#pragma unroll 1
    for (int l4 = 0; l4 < CLEN; l4 += 4) {
        const float4 d4 = *(const float4*)(dl + l4);
        const float4 u4 = *(const float4*)(us + l4);
        const float dts[4] = {d4.x, d4.y, d4.z, d4.w};
        const float uus[4] = {u4.x, u4.y, u4.z, u4.w};
#pragma unroll
        for (int j = 0; j < 4; j++) {
            const float4* Bp = (const float4*)(xb + (size_t)(l4 + j) * 64);
            float Bv[DSTATE];
#pragma unroll
            for (int q = 0; q < 4; q++) {
                float4 v = Bp[q];
                Bv[q * 4 + 0] = v.x; Bv[q * 4 + 1] = v.y;
                Bv[q * 4 + 2] = v.z; Bv[q * 4 + 3] = v.w;
            }
            const float dt = dts[j];
            const float dtu = dt * uus[j];
            sdt += dt;
#pragma unroll
            for (int n = 0; n < DSTATE; n++) {
                const float dA = __expf(dt * A_dn[n]);
                h[n] = fmaf(dA, h[n], dtu * Bv[n]);
            }
        }
    }

    float* he = g_hend  + ((size_t)t * NCHAN + ch) * DSTATE;
    float* de = g_decay + ((size_t)t * NCHAN + ch) * DSTATE;
#pragma unroll
    for (int q = 0; q < 4; q++)
        *(float4*)(he + q * 4) =
            make_float4(h[q * 4], h[q * 4 + 1], h[q * 4 + 2], h[q * 4 + 3]);
#pragma unroll
    for (int q = 0; q < 4; q++) {
        float4 v;
        v.x = __expf(sdt * A_dn[q * 4 + 0]);
        v.y = __expf(sdt * A_dn[q * 4 + 1]);
        v.z = __expf(sdt * A_dn[q * 4 + 2]);
        v.w = __expf(sdt * A_dn[q * 4 + 3]);
        *(float4*)(de + q * 4) = v;
    }
}

// ---------------------------------------------------------------------------
// Scan phase B: compose chunk states serially over T chunks.
// ---------------------------------------------------------------------------
__global__ void __launch_bounds__(256)
scan_phaseB()
{
    const int id = blockIdx.x * 256 + threadIdx.x;   // 0..NCHAN*DSTATE-1
    float h = 0.f;
#pragma unroll
    for (int t = 0; t < TCHUNK; t++) {
        const size_t o = (size_t)t * NCHAN * DSTATE + id;
        g_h0[o] = h;
        h = g_decay[o] * h + g_hend[o];
    }
}

// ---------------------------------------------------------------------------
// Scan phase C: thread-per-channel full scan from h0 -> y.  No shfl:
// y = sum_n h[n]*C[n] is a sequential in-register dot over 16 states.
// Grid (NCHAN/128, TCHUNK), 128 threads.
// ---------------------------------------------------------------------------
__global__ void __launch_bounds__(128)
scan_phaseC(const float* __restrict__ A_log,
            const float* __restrict__ D_param)
{
    const int tid = threadIdx.x;
    const int ch = blockIdx.x * 128 + tid;
    const int t  = blockIdx.y;
    const int b  = ch >> 10;
    const int d  = ch & (DINNER - 1);

    float A_dn[DSTATE];
#pragma unroll
    for (int q = 0; q < 4; q++) {
        float4 a4 = *(const float4*)&A_log[d * DSTATE + q * 4];
        A_dn[q * 4 + 0] = -__expf(a4.x);
        A_dn[q * 4 + 1] = -__expf(a4.y);
        A_dn[q * 4 + 2] = -__expf(a4.z);
        A_dn[q * 4 + 3] = -__expf(a4.w);
    }
    const float Dd = D_param[d];

    const float* dl = g_deltat + (size_t)ch * SEQLEN + t * CLEN;
    const float* us = g_xst    + (size_t)ch * SEQLEN + t * CLEN;
    const float* zp = g_zt     + (size_t)ch * SEQLEN + t * CLEN;
    const float* xr = g_xdbl + ((size_t)b * SEQLEN + t * CLEN) * 64;
    float* yp = g_y + ((size_t)b * SEQLEN + t * CLEN) * DINNER + d;

    float h[DSTATE];
    {
        const float* h0 = g_h0 + ((size_t)t * NCHAN + ch) * DSTATE;
#pragma unroll
        for (int q = 0; q < 4; q++) {
            float4 v = *(const float4*)(h0 + q * 4);
            h[q * 4 + 0] = v.x; h[q * 4 + 1] = v.y;
            h[q * 4 + 2] = v.z; h[q * 4 + 3] = v.w;
        }
    }

#pragma unroll 1
    for (int l4 = 0; l4 < CLEN; l4 += 4) {
        const float4 d4 = *(const float4*)(dl + l4);
        const float4 u4 = *(const float4*)(us + l4);
        const float4 z4 = *(const float4*)(zp + l4);
        const float dts[4] = {d4.x, d4.y, d4.z, d4.w};
        const float uus[4] = {u4.x, u4.y, u4.z, u4.w};
        const float zzs[4] = {z4.x, z4.y, z4.z, z4.w};
#pragma unroll
        for (int j = 0; j < 4; j++) {
            const float4* Rp = (const float4*)(xr + (size_t)(l4 + j) * 64 + 32);
            float Bv[DSTATE], Cv[DSTATE];
#pragma unroll
            for (int q = 0; q < 4; q++) {
                float4 v = Rp[q];
                Bv[q * 4 + 0] = v.x; Bv[q * 4 + 1] = v.y;
                Bv[q * 4 + 2] = v.z; Bv[q * 4 + 3] = v.w;
                float4 w = Rp[q + 4];
                Cv[q * 4 + 0] = w.x; Cv[q * 4 + 1] = w.y;
                Cv[q * 4 + 2] = w.z; Cv[q * 4 + 3] = w.w;
            }
            const float dt = dts[j];
            const float dtu = dt * uus[j];
            float y = 0.f;
#pragma unroll
            for (int n = 0; n < DSTATE; n++) {
                const float dA = __expf(dt * A_dn[n]);
                h[n] = fmaf(dA, h[n], dtu * Bv[n]);
                y = fmaf(h[n], Cv[n], y);
            }
            const float z = zzs[j];
            const float sz = z / (1.f + __expf(-z));
            const float v = (y + uus[j] * Dd) * sz;
            yp[(size_t)(l4 + j) * DINNER] = __uint_as_float(f2tf32(v));
        }
    }
}

// ---------------------------------------------------------------------------
extern "C" void kernel_launch(void* const* d_in, const int* in_sizes, int n_in,
                              void* d_out, int out_size)
{
    const float* x          = (const float*)d_in[0];
    const float* in_proj_w  = (const float*)d_in[1];
    const float* conv_w     = (const float*)d_in[2];
    const float* conv_b     = (const float*)d_in[3];
    const float* x_proj_w   = (const float*)d_in[4];
    const float* dt_proj_w  = (const float*)d_in[5];
    const float* dt_proj_b  = (const float*)d_in[6];
    const float* A_log      = (const float*)d_in[7];
    const float* D_param    = (const float*)d_in[8];
    const float* out_proj_w = (const float*)d_in[9];
    float* out = (float*)d_out;

    // 0) x, in_proj_w -> tf32 scratch
    cvt_pre<<<3 * 1024 * 1024 / 4 / 256, 256>>>(x, in_proj_w);

    // 1) in_proj (tf32 mma, cp.async) -> g_xz [4096,2048]
    gemm_pipe<1><<<dim3(2 * DINNER / 128, MROWS / 128), 256>>>(nullptr);

    // 2+3) conv+silu fused with x_proj -> g_xst, g_zt, g_xdbl (+ w6 cvt)
    conv_xproj<<<MROWS / 32, 256>>>(conv_w, conv_b, x_proj_w, out_proj_w);

    // 4) dt_proj + softplus -> g_deltat [2048 ch][2048 l]
    gemm_nt4<<<dim3(DINNER / 64, MROWS / 64), 256>>>(dt_proj_w, dt_proj_b);

    // 5a) chunk summaries (thread-per-channel)
    scan_phaseA<<<dim3(NCHAN / 128, TCHUNK), 128>>>(A_log);
    // 5b) chunk-state composition
    scan_phaseB<<<NCHAN * DSTATE / 256, 256>>>();
    // 5c) per-chunk scan from h0 -> g_y (thread-per-channel)
    scan_phaseC<<<dim3(NCHAN / 128, TCHUNK), 128>>>(A_log, D_param);

    // 6) out_proj (tf32 mma, cp.async) -> out [4096,512]
    gemm_pipe<6><<<dim3(DMODEL / 128, MROWS / 128), 256>>>(out);
}

// round 12
// speedup vs baseline: 3.5314x; 1.0338x over previous
#include <cuda_runtime.h>
#include <cuda_bf16.h>
#include <cstdint>

// ---------------------------------------------------------------------------
// Mamba block forward.  B=2, L=2048, d_model=512, d_inner=1024, d_state=16,
// dt_rank=32, d_conv=4.
// Launches: 1 cvt_k<0>     x -> tf32
//           2 cvt_k<1>     in_proj_w -> tf32
//           3 cvt_k<2>     out_proj_w -> tf32
//           4 gemm_tf<1>   in_proj (tf32 mma, BK=32 SW128, cp.async)  [profiled]
//           5 conv_xproj   conv+silu + x_proj fused; xs_t/z_t transposed
//           6 gemm_nt4     dt_proj + softplus -> delta_t (transposed)
//           7 scan_phaseA  thread-per-channel chunk summaries (h in regs)
//           8 scan_phaseB  chunk-state composition -> h0 per chunk
//           9 scan_phaseC  thread-per-channel scan from h0 -> y (no shfl)
//          10 gemm_tf<6>   out_proj (tf32 mma)
// ---------------------------------------------------------------------------

#define BATCH    2
#define SEQLEN   2048
#define DMODEL   512
#define DINNER   1024
#define DSTATE   16
#define DTRANK   32
#define DCONV    4
#define MROWS    (BATCH * SEQLEN)        // 4096
#define NCHAN    (BATCH * DINNER)        // 2048 scan channels
#define TCHUNK   32                      // scan chunks along L
#define CLEN     (SEQLEN / TCHUNK)       // 64 steps per chunk

// Scratch (device-global; no runtime allocation allowed)
__device__ float g_xz[(size_t)MROWS * 2 * DINNER];    // [4096, 2048]  xs | z
__device__ float g_xst[(size_t)NCHAN * SEQLEN];       // xs transposed [ch][l]
__device__ float g_zt[(size_t)NCHAN * SEQLEN];        // z transposed [ch][l]
__device__ float g_xdbl[(size_t)MROWS * 64];          // [4096, 64]
__device__ float g_deltat[(size_t)NCHAN * SEQLEN];    // delta transposed [ch][l]
__device__ float g_y[(size_t)MROWS * DINNER];         // scan output (tf32-rounded)
__device__ uint32_t g_w6tf[(size_t)DMODEL * DINNER];  // out_proj_w in tf32
__device__ uint32_t g_x1tf[(size_t)MROWS * DMODEL];   // x in tf32
__device__ uint32_t g_w1tf[(size_t)2 * DINNER * DMODEL]; // in_proj_w in tf32
__device__ float g_hend[(size_t)TCHUNK * NCHAN * DSTATE];
__device__ float g_decay[(size_t)TCHUNK * NCHAN * DSTATE];
__device__ float g_h0[(size_t)TCHUNK * NCHAN * DSTATE];

// ---------------------------------------------------------------------------
__device__ __forceinline__ uint32_t f2tf32(float f) {
    uint32_t r;
    asm("cvt.rna.tf32.f32 %0, %1;" : "=r"(r) : "f"(f));
    return r;
}

__device__ __forceinline__ void mma_tf32(float c[4], const uint32_t a[4],
                                         uint32_t b0, uint32_t b1) {
    asm volatile(
        "mma.sync.aligned.m16n8k8.row.col.f32.tf32.tf32.f32 "
        "{%0,%1,%2,%3}, {%4,%5,%6,%7}, {%8,%9}, {%0,%1,%2,%3};"
        : "+f"(c[0]), "+f"(c[1]), "+f"(c[2]), "+f"(c[3])
        : "r"(a[0]), "r"(a[1]), "r"(a[2]), "r"(a[3]), "r"(b0), "r"(b1));
}

__device__ __forceinline__ void cp16(uint32_t dst_smem, const void* src) {
    asm volatile("cp.async.cg.shared.global [%0], [%1], 16;\n"
                 :: "r"(dst_smem), "l"(src));
}

// ---------------------------------------------------------------------------
// Prepass: WHICH 0: x -> g_x1tf (2M), 1: in_proj_w -> g_w1tf (1M),
//          2: out_proj_w -> g_w6tf (512K).  float4 per thread.
// ---------------------------------------------------------------------------
template <int WHICH>
__global__ void __launch_bounds__(256)
cvt_k(const float* __restrict__ src)
{
    uint32_t* dst = (WHICH == 0) ? g_x1tf : (WHICH == 1) ? g_w1tf : g_w6tf;
    const size_t i4 = ((size_t)blockIdx.x * 256 + threadIdx.x) * 4;
    float4 v = *(const float4*)&src[i4];
    uint4 p;
    p.x = f2tf32(v.x); p.y = f2tf32(v.y);
    p.z = f2tf32(v.z); p.w = f2tf32(v.w);
    *(uint4*)&dst[i4] = p;
}

// ---------------------------------------------------------------------------
// tf32 mma NT GEMM, BK=32, SW128-swizzled smem (128B rows, no padding),
// 2-stage cp.async.  BM=BN=128, 256 threads = 8 warps, warp tile 32x64.
//   STAGE 1: A=g_x1tf, W=g_w1tf, C=g_xz, K=512,  ldc=2048
//   STAGE 6: A=g_y,    W=g_w6tf, C=out,  K=1024, ldc=512
// Dynamic smem: 1KB align slack + 4 x 16KB tiles (A0,A1,B0,B1) = 66560 B.
// Swizzle: 16B-group index (3 bits) ^= row&7; per-lane group offsets are
// precomputed, so the inner loop has zero extra ALU.
// ---------------------------------------------------------------------------
#define GTF_SMEM (1024 + 4 * 16384)

template <int STAGE>
__global__ void __launch_bounds__(256)
gemm_tf(float* __restrict__ Cp)
{
    constexpr int K   = (STAGE == 1) ? DMODEL : DINNER;
    constexpr int ldc = (STAGE == 1) ? 2 * DINNER : DMODEL;
    constexpr int NC  = K / 32;                        // 32-K chunks

    const uint32_t* Ab = (STAGE == 1) ? g_x1tf : (const uint32_t*)g_y;
    const uint32_t* Wb = (STAGE == 1) ? g_w1tf : g_w6tf;
    float* C = (STAGE == 1) ? g_xz : Cp;

    extern __shared__ char dsm[];
    uint32_t* sbase = (uint32_t*)(((uintptr_t)dsm + 1023) & ~(uintptr_t)1023);
    uint32_t* const SA0 = sbase;                       // 4096 u32 = 16KB each
    uint32_t* const SA1 = sbase + 4096;
    uint32_t* const SB0 = sbase + 8192;
    uint32_t* const SB1 = sbase + 12288;

    const int tid = threadIdx.x;
    const int lane = tid & 31;
    const int wid = tid >> 5;
    const int wm = (wid & 3) * 32;
    const int wn = (wid >> 2) * 64;
    const int g  = lane >> 2;
    const int tg = lane & 3;
    const int m0 = blockIdx.y * 128;
    const int n0 = blockIdx.x * 128;

    // per-lane swizzled group offsets: k-col = q*4 + tg  ->  u32 offset
    int goff[8];
#pragma unroll
    for (int q = 0; q < 8; q++) goff[q] = ((q ^ g) << 2) + tg;

    auto fill = [&](uint32_t* sa, uint32_t* sb, int kc) {
        const int k0 = kc * 32;
        const int cs = tid & 7;
#pragma unroll
        for (int it = 0; it < 4; it++) {
            const int r = (tid >> 3) + it * 32;        // 0..127
            const uint32_t off = (uint32_t)(r * 32 + ((cs ^ (r & 7)) << 2));
            cp16((uint32_t)__cvta_generic_to_shared(sa + off),
                 Ab + (size_t)(m0 + r) * K + k0 + cs * 4);
            cp16((uint32_t)__cvta_generic_to_shared(sb + off),
                 Wb + (size_t)(n0 + r) * K + k0 + cs * 4);
        }
    };

    float c[2][8][4];
#pragma unroll
    for (int i = 0; i < 2; i++)
#pragma unroll
        for (int j = 0; j < 8; j++)
#pragma unroll
            for (int r = 0; r < 4; r++) c[i][j][r] = 0.f;

    fill(SA0, SB0, 0); asm volatile("cp.async.commit_group;\n" ::);
    fill(SA1, SB1, 1); asm volatile("cp.async.commit_group;\n" ::);

#pragma unroll 1
    for (int cchunk = 0; cchunk < NC; cchunk++) {
        const int s = cchunk & 1;
        if (cchunk + 1 < NC) asm volatile("cp.async.wait_group 1;\n" ::);
        else                 asm volatile("cp.async.wait_group 0;\n" ::);
        __syncthreads();

        const uint32_t* As = s ? SA1 : SA0;
        const uint32_t* Bs = s ? SB1 : SB0;
#pragma unroll
        for (int kk = 0; kk < 4; kk++) {               // 4 x K=8 per chunk
            const int q0 = kk * 2;
            uint32_t a[2][4];
#pragma unroll
            for (int i = 0; i < 2; i++) {
                const int r0 = (wm + i * 16 + g) * 32;
                a[i][0] = As[r0 + goff[q0]];
                a[i][1] = As[r0 + 256 + goff[q0]];     // +8 rows
                a[i][2] = As[r0 + goff[q0 + 1]];
                a[i][3] = As[r0 + 256 + goff[q0 + 1]];
            }
#pragma unroll
            for (int j = 0; j < 8; j++) {
                const int rb = (wn + j * 8 + g) * 32;
                const uint32_t b0 = Bs[rb + goff[q0]];
                const uint32_t b1 = Bs[rb + goff[q0 + 1]];
                mma_tf32(c[0][j], a[0], b0, b1);
                mma_tf32(c[1][j], a[1], b0, b1);
            }
        }
        __syncthreads();

        if (cchunk + 2 < NC) {
            fill(s ? SA1 : SA0, s ? SB1 : SB0, cchunk + 2);
            asm volatile("cp.async.commit_group;\n" ::);
        }
    }

    // epilogue
#pragma unroll
    for (int i = 0; i < 2; i++) {
        const int mrow0 = m0 + wm + i * 16 + g;
#pragma unroll
        for (int j = 0; j < 8; j++) {
            const int ncol = n0 + wn + j * 8 + 2 * tg;
            *(float2*)&C[(size_t)mrow0 * ldc + ncol] =
                make_float2(c[i][j][0], c[i][j][1]);
            *(float2*)&C[(size_t)(mrow0 + 8) * ldc + ncol] =
                make_float2(c[i][j][2], c[i][j][3]);
        }
    }
}

// ---------------------------------------------------------------------------
// Stage 2+3 fused: conv1d+SiLU, x_proj GEMM; writes xs_t and z_t transposed.
// ---------------------------------------------------------------------------
__global__ void __launch_bounds__(256)
conv_xproj(const float* __restrict__ conv_w,
           const float* __restrict__ conv_b,
           const float* __restrict__ x_proj_w)
{
    __shared__ float sxs[32][68];
    __shared__ float sw[64][68];
    __shared__ float sz[32][68];

    const int tid = threadIdx.x;
    const int bl0 = blockIdx.x * 32;
    const int b   = bl0 >> 11;
    const int l0  = bl0 & 2047;
    const int tx = tid & 15;
    const int ty = tid >> 4;

    float acc[2][4];
#pragma unroll
    for (int i = 0; i < 2; i++)
#pragma unroll
        for (int j = 0; j < 4; j++) acc[i][j] = 0.f;

#pragma unroll 1
    for (int d0 = 0; d0 < DINNER; d0 += 64) {
        __syncthreads();
#pragma unroll
        for (int it = 0; it < 4; it++) {
            const int idx = tid + it * 256;
            const int e = idx >> 4, c4 = (idx & 15) * 4;
            *(float4*)&sw[e][c4] =
                *(const float4*)&x_proj_w[(size_t)e * DINNER + d0 + c4];
        }
#pragma unroll
        for (int it = 0; it < 8; it++) {
            const int idx = tid + it * 256;
            const int r = idx >> 6, dc = idx & 63;
            const int bl = bl0 + r;
            const int l = bl & (SEQLEN - 1);
            const int d = d0 + dc;
            float a = conv_b[d];
#pragma unroll
            for (int j = 0; j < DCONV; j++) {
                const int ls = l - (DCONV - 1) + j;
                if (ls >= 0)
                    a = fmaf(g_xz[(size_t)(bl - (DCONV - 1) + j) * (2 * DINNER) + d],
                             conv_w[d * DCONV + j], a);
            }
            sxs[r][dc] = a / (1.f + __expf(-a));     // SiLU
            sz[r][dc] = g_xz[(size_t)bl * (2 * DINNER) + DINNER + d];
        }
        __syncthreads();
        {
            const int dloc = tid >> 2;
            const int lq = (tid & 3) * 8;
            const size_t row = (size_t)(b * DINNER + d0 + dloc) * SEQLEN + l0 + lq;
            float4 v0, v1;
            v0.x = sxs[lq + 0][dloc]; v0.y = sxs[lq + 1][dloc];
            v0.z = sxs[lq + 2][dloc]; v0.w = sxs[lq + 3][dloc];
            v1.x = sxs[lq + 4][dloc]; v1.y = sxs[lq + 5][dloc];
            v1.z = sxs[lq + 6][dloc]; v1.w = sxs[lq + 7][dloc];
            *(float4*)&g_xst[row] = v0;
            *(float4*)&g_xst[row + 4] = v1;
            v0.x = sz[lq + 0][dloc]; v0.y = sz[lq + 1][dloc];
            v0.z = sz[lq + 2][dloc]; v0.w = sz[lq + 3][dloc];
            v1.x = sz[lq + 4][dloc]; v1.y = sz[lq + 5][dloc];
            v1.z = sz[lq + 6][dloc]; v1.w = sz[lq + 7][dloc];
            *(float4*)&g_zt[row] = v0;
            *(float4*)&g_zt[row + 4] = v1;
        }
#pragma unroll
        for (int kk = 0; kk < 64; kk++) {
            float ar[2], br[4];
#pragma unroll
            for (int i = 0; i < 2; i++) ar[i] = sxs[ty * 2 + i][kk];
#pragma unroll
            for (int j = 0; j < 4; j++) br[j] = sw[tx * 4 + j][kk];
#pragma unroll
            for (int i = 0; i < 2; i++)
#pragma unroll
                for (int j = 0; j < 4; j++)
                    acc[i][j] = fmaf(ar[i], br[j], acc[i][j]);
        }
    }

#pragma unroll
    for (int i = 0; i < 2; i++)
#pragma unroll
        for (int j = 0; j < 4; j++)
            g_xdbl[(size_t)(bl0 + ty * 2 + i) * 64 + tx * 4 + j] = acc[i][j];
}

// ---------------------------------------------------------------------------
// Stage 4: dt_proj + softplus -> delta_t[ch][l] (transposed write).
// ---------------------------------------------------------------------------
__global__ void __launch_bounds__(256)
gemm_nt4(const float* __restrict__ W, const float* __restrict__ bias)
{
    constexpr int BM = 64, BN = 64, BK = 16;
    constexpr int lda = 64, ldw = DTRANK, K = DTRANK;
    const float* A = g_xdbl;

    __shared__ float As[BK][BM];
    __shared__ float Bs[BK][BN];

    const int tid = threadIdx.x;
    const int m0 = blockIdx.y * BM;
    const int n0 = blockIdx.x * BN;
    const int tx = tid & 15;
    const int ty = tid >> 4;
    const int lrow = tid >> 2;
    const int lc4 = (tid & 3) * 4;

    float acc[4][4];
#pragma unroll
    for (int i = 0; i < 4; i++)
#pragma unroll
        for (int j = 0; j < 4; j++) acc[i][j] = 0.f;

    const float* Arow = A + (size_t)(m0 + lrow) * lda + lc4;
    const float* Wrow = W + (size_t)(n0 + lrow) * ldw + lc4;

#pragma unroll 1
    for (int k0 = 0; k0 < K; k0 += BK) {
        float4 av = *(const float4*)(Arow + k0);
        float4 wv = *(const float4*)(Wrow + k0);
        __syncthreads();
        As[lc4 + 0][lrow] = av.x; As[lc4 + 1][lrow] = av.y;
        As[lc4 + 2][lrow] = av.z; As[lc4 + 3][lrow] = av.w;
        Bs[lc4 + 0][lrow] = wv.x; Bs[lc4 + 1][lrow] = wv.y;
        Bs[lc4 + 2][lrow] = wv.z; Bs[lc4 + 3][lrow] = wv.w;
        __syncthreads();
#pragma unroll
        for (int kk = 0; kk < BK; kk++) {
            float4 a4 = *(const float4*)&As[kk][ty * 4];
            float4 b4 = *(const float4*)&Bs[kk][tx * 4];
            float ar[4] = {a4.x, a4.y, a4.z, a4.w};
            float br[4] = {b4.x, b4.y, b4.z, b4.w};
#pragma unroll
            for (int i = 0; i < 4; i++)
#pragma unroll
                for (int j = 0; j < 4; j++)
                    acc[i][j] = fmaf(ar[i], br[j], acc[i][j]);
        }
    }

    const int b = m0 >> 11;
    const int lb = (m0 & 2047) + ty * 4;
#pragma unroll
    for (int j = 0; j < 4; j++) {
        const int n = n0 + tx * 4 + j;
        float sp[4];
#pragma unroll
        for (int i = 0; i < 4; i++) {
            float v = acc[i][j] + bias[n];
            sp[i] = (v > 20.f) ? v : log1pf(__expf(v));
        }
        *(float4*)&g_deltat[(size_t)(b * DINNER + n) * SEQLEN + lb] =
            make_float4(sp[0], sp[1], sp[2], sp[3]);
    }
}

// ---------------------------------------------------------------------------
// Scan phase A: thread-per-channel; all 16 states in registers.
// ---------------------------------------------------------------------------
__global__ void __launch_bounds__(128)
scan_phaseA(const float* __restrict__ A_log)
{
    const int tid = threadIdx.x;
    const int ch = blockIdx.x * 128 + tid;     // global channel
    const int t  = blockIdx.y;
    const int b  = ch >> 10;
    const int d  = ch & (DINNER - 1);

    float A_dn[DSTATE];
#pragma unroll
    for (int q = 0; q < 4; q++) {
        float4 a4 = *(const float4*)&A_log[d * DSTATE + q * 4];
        A_dn[q * 4 + 0] = -__expf(a4.x);
        A_dn[q * 4 + 1] = -__expf(a4.y);
        A_dn[q * 4 + 2] = -__expf(a4.z);
        A_dn[q * 4 + 3] = -__expf(a4.w);
    }

    const float* dl = g_deltat + (size_t)ch * SEQLEN + t * CLEN;
    const float* us = g_xst    + (size_t)ch * SEQLEN + t * CLEN;
    const float* xb = g_xdbl + ((size_t)b * SEQLEN + t * CLEN) * 64 + 32;

    float h[DSTATE];
#pragma unroll
    for (int n = 0; n < DSTATE; n++) h[n] = 0.f;
    float sdt = 0.f;

#pragma unroll 1
    for (int l4 = 0; l4 < CLEN; l4 += 4) {
        const float4 d4 = *(const float4*)(dl + l4);
        const float4 u4 = *(const float4*)(us + l4);
        const float dts[4] = {d4.x, d4.y, d4.z, d4.w};
        const float uus[4] = {u4.x, u4.y, u4.z, u4.w};
#pragma unroll
        for (int j = 0; j < 4; j++) {
            const float4* Bp = (const float4*)(xb + (size_t)(l4 + j) * 64);
            float Bv[DSTATE];
#pragma unroll
            for (int q = 0; q < 4; q++) {
                float4 v = Bp[q];
                Bv[q * 4 + 0] = v.x; Bv[q * 4 + 1] = v.y;
                Bv[q * 4 + 2] = v.z; Bv[q * 4 + 3] = v.w;
            }
            const float dt = dts[j];
            const float dtu = dt * uus[j];
            sdt += dt;
#pragma unroll
            for (int n = 0; n < DSTATE; n++) {
                const float dA = __expf(dt * A_dn[n]);
                h[n] = fmaf(dA, h[n], dtu * Bv[n]);
            }
        }
    }

    float* he = g_hend  + ((size_t)t * NCHAN + ch) * DSTATE;
    float* de = g_decay + ((size_t)t * NCHAN + ch) * DSTATE;
#pragma unroll
    for (int q = 0; q < 4; q++)
        *(float4*)(he + q * 4) =
            make_float4(h[q * 4], h[q * 4 + 1], h[q * 4 + 2], h[q * 4 + 3]);
#pragma unroll
    for (int q = 0; q < 4; q++) {
        float4 v;
        v.x = __expf(sdt * A_dn[q * 4 + 0]);
        v.y = __expf(sdt * A_dn[q * 4 + 1]);
        v.z = __expf(sdt * A_dn[q * 4 + 2]);
        v.w = __expf(sdt * A_dn[q * 4 + 3]);
        *(float4*)(de + q * 4) = v;
    }
}

// ---------------------------------------------------------------------------
// Scan phase B: compose chunk states serially over T chunks.
// ---------------------------------------------------------------------------
__global__ void __launch_bounds__(256)
scan_phaseB()
{
    const int id = blockIdx.x * 256 + threadIdx.x;   // 0..NCHAN*DSTATE-1
    float h = 0.f;
#pragma unroll
    for (int t = 0; t < TCHUNK; t++) {
        const size_t o = (size_t)t * NCHAN * DSTATE + id;
        g_h0[o] = h;
        h = g_decay[o] * h + g_hend[o];
    }
}

// ---------------------------------------------------------------------------
// Scan phase C: thread-per-channel full scan from h0 -> y (no shfl).
// ---------------------------------------------------------------------------
__global__ void __launch_bounds__(128)
scan_phaseC(const float* __restrict__ A_log,
            const float* __restrict__ D_param)
{
    const int tid = threadIdx.x;
    const int ch = blockIdx.x * 128 + tid;
    const int t  = blockIdx.y;
    const int b  = ch >> 10;
    const int d  = ch & (DINNER - 1);

    float A_dn[DSTATE];
#pragma unroll
    for (int q = 0; q < 4; q++) {
        float4 a4 = *(const float4*)&A_log[d * DSTATE + q * 4];
        A_dn[q * 4 + 0] = -__expf(a4.x);
        A_dn[q * 4 + 1] = -__expf(a4.y);
        A_dn[q * 4 + 2] = -__expf(a4.z);
        A_dn[q * 4 + 3] = -__expf(a4.w);
    }
    const float Dd = D_param[d];

    const float* dl = g_deltat + (size_t)ch * SEQLEN + t * CLEN;
    const float* us = g_xst    + (size_t)ch * SEQLEN + t * CLEN;
    const float* zp = g_zt     + (size_t)ch * SEQLEN + t * CLEN;
    const float* xr = g_xdbl + ((size_t)b * SEQLEN + t * CLEN) * 64;
    float* yp = g_y + ((size_t)b * SEQLEN + t * CLEN) * DINNER + d;

    float h[DSTATE];
    {
        const float* h0 = g_h0 + ((size_t)t * NCHAN + ch) * DSTATE;
#pragma unroll
        for (int q = 0; q < 4; q++) {
            float4 v = *(const float4*)(h0 + q * 4);
            h[q * 4 + 0] = v.x; h[q * 4 + 1] = v.y;
            h[q * 4 + 2] = v.z; h[q * 4 + 3] = v.w;
        }
    }

#pragma unroll 1
    for (int l4 = 0; l4 < CLEN; l4 += 4) {
        const float4 d4 = *(const float4*)(dl + l4);
        const float4 u4 = *(const float4*)(us + l4);
        const float4 z4 = *(const float4*)(zp + l4);
        const float dts[4] = {d4.x, d4.y, d4.z, d4.w};
        const float uus[4] = {u4.x, u4.y, u4.z, u4.w};
        const float zzs[4] = {z4.x, z4.y, z4.z, z4.w};
#pragma unroll
        for (int j = 0; j < 4; j++) {
            const float4* Rp = (const float4*)(xr + (size_t)(l4 + j) * 64 + 32);
            float Bv[DSTATE], Cv[DSTATE];
#pragma unroll
            for (int q = 0; q < 4; q++) {
                float4 v = Rp[q];
                Bv[q * 4 + 0] = v.x; Bv[q * 4 + 1] = v.y;
                Bv[q * 4 + 2] = v.z; Bv[q * 4 + 3] = v.w;
                float4 w = Rp[q + 4];
                Cv[q * 4 + 0] = w.x; Cv[q * 4 + 1] = w.y;
                Cv[q * 4 + 2] = w.z; Cv[q * 4 + 3] = w.w;
            }
            const float dt = dts[j];
            const float dtu = dt * uus[j];
            float y = 0.f;
#pragma unroll
            for (int n = 0; n < DSTATE; n++) {
                const float dA = __expf(dt * A_dn[n]);
                h[n] = fmaf(dA, h[n], dtu * Bv[n]);
                y = fmaf(h[n], Cv[n], y);
            }
            const float z = zzs[j];
            const float sz = z / (1.f + __expf(-z));
            const float v = (y + uus[j] * Dd) * sz;
            yp[(size_t)(l4 + j) * DINNER] = __uint_as_float(f2tf32(v));
        }
    }
}

// ---------------------------------------------------------------------------
extern "C" void kernel_launch(void* const* d_in, const int* in_sizes, int n_in,
                              void* d_out, int out_size)
{
    const float* x          = (const float*)d_in[0];
    const float* in_proj_w  = (const float*)d_in[1];
    const float* conv_w     = (const float*)d_in[2];
    const float* conv_b     = (const float*)d_in[3];
    const float* x_proj_w   = (const float*)d_in[4];
    const float* dt_proj_w  = (const float*)d_in[5];
    const float* dt_proj_b  = (const float*)d_in[6];
    const float* A_log      = (const float*)d_in[7];
    const float* D_param    = (const float*)d_in[8];
    const float* out_proj_w = (const float*)d_in[9];
    float* out = (float*)d_out;

    cudaFuncSetAttribute(gemm_tf<1>, cudaFuncAttributeMaxDynamicSharedMemorySize,
                         GTF_SMEM);
    cudaFuncSetAttribute(gemm_tf<6>, cudaFuncAttributeMaxDynamicSharedMemorySize,
                         GTF_SMEM);

    // 1-3) tf32 prepasses
    cvt_k<0><<<(MROWS * DMODEL) / 1024, 256>>>(x);
    cvt_k<1><<<(2 * DINNER * DMODEL) / 1024, 256>>>(in_proj_w);
    cvt_k<2><<<(DMODEL * DINNER) / 1024, 256>>>(out_proj_w);

    // 4) in_proj (tf32 mma, BK=32) -> g_xz  [capture slot]
    gemm_tf<1><<<dim3(2 * DINNER / 128, MROWS / 128), 256, GTF_SMEM>>>(nullptr);

    // 5) conv+silu fused with x_proj -> g_xst, g_zt, g_xdbl
    conv_xproj<<<MROWS / 32, 256>>>(conv_w, conv_b, x_proj_w);

    // 6) dt_proj + softplus -> g_deltat
    gemm_nt4<<<dim3(DINNER / 64, MROWS / 64), 256>>>(dt_proj_w, dt_proj_b);

    // 7-9) chunked selective scan
    scan_phaseA<<<dim3(NCHAN / 128, TCHUNK), 128>>>(A_log);
    scan_phaseB<<<NCHAN * DSTATE / 256, 256>>>();
    scan_phaseC<<<dim3(NCHAN / 128, TCHUNK), 128>>>(A_log, D_param);

    // 10) out_proj (tf32 mma, BK=32) -> out
    gemm_tf<6><<<dim3(DMODEL / 128, MROWS / 128), 256, GTF_SMEM>>>(out);
}